// round 1
// baseline (speedup 1.0000x reference)
#include <cuda_runtime.h>
#include <cuda_bf16.h>
#include <math.h>

// Problem constants
#define BB 2
#define SS 2048
#define NTOK (BB*SS)            // 4096
#define HIDDEN 4096
#define H 32
#define HK 8
#define D 128
#define QKV_COLS ((H + 2*HK) * D)   // 6144
#define K_OFF (H*D)                 // 4096
#define V_OFF (H*D + HK*D)          // 5120
#define SCALE 0.08838834764831845f  // 1/sqrt(128)

// Scratch (static device globals — no runtime allocation)
__device__ float g_qkv[(size_t)NTOK * QKV_COLS];   // ~100 MB
__device__ float g_attn[(size_t)NTOK * (H*D)];     // ~67 MB

// ---------------------------------------------------------------------------
// SGEMM: C[M,N] = A[M,K] @ B[K,N], all row-major fp32.
// 128x128 block tile, BK=16, 256 threads, 8x8 per-thread micro-tile.
// Requires M,N % 128 == 0, K % 16 == 0 (true for all our shapes).
// ---------------------------------------------------------------------------
__global__ __launch_bounds__(256) void sgemm_kernel(
    const float* __restrict__ A, const float* __restrict__ B,
    float* __restrict__ C, int M, int N, int K)
{
    __shared__ float As[16][128];   // transposed A tile: As[k][m]
    __shared__ float Bs[16][128];   // Bs[k][n]

    const int tid = threadIdx.x;
    const int bm = blockIdx.y * 128;
    const int bn = blockIdx.x * 128;

    // micro-tile coords: rows {tr..tr+3, tr+64..tr+67}, cols {tc.., tc+64..}
    const int tr = (tid / 16) * 4;
    const int tc = (tid % 16) * 4;

    // global load mapping
    const int arow = tid / 4;          // 0..63 (two passes: +0, +64)
    const int acol = (tid % 4) * 4;    // 0,4,8,12
    const int brow = tid / 32;         // 0..7 (two passes: +0, +8)
    const int bcol = (tid % 32) * 4;   // 0..124

    float acc[8][8];
#pragma unroll
    for (int i = 0; i < 8; i++)
#pragma unroll
        for (int j = 0; j < 8; j++) acc[i][j] = 0.f;

    for (int k0 = 0; k0 < K; k0 += 16) {
        // load A tile (transposed into smem)
#pragma unroll
        for (int p = 0; p < 2; p++) {
            float4 v = *(const float4*)&A[(size_t)(bm + arow + 64*p) * K + k0 + acol];
            As[acol+0][arow + 64*p] = v.x;
            As[acol+1][arow + 64*p] = v.y;
            As[acol+2][arow + 64*p] = v.z;
            As[acol+3][arow + 64*p] = v.w;
        }
        // load B tile
#pragma unroll
        for (int p = 0; p < 2; p++) {
            *(float4*)&Bs[brow + 8*p][bcol] =
                *(const float4*)&B[(size_t)(k0 + brow + 8*p) * N + bn + bcol];
        }
        __syncthreads();

#pragma unroll
        for (int kk = 0; kk < 16; kk++) {
            float ra[8], rb[8];
            *(float4*)&ra[0] = *(float4*)&As[kk][tr];
            *(float4*)&ra[4] = *(float4*)&As[kk][tr + 64];
            *(float4*)&rb[0] = *(float4*)&Bs[kk][tc];
            *(float4*)&rb[4] = *(float4*)&Bs[kk][tc + 64];
#pragma unroll
            for (int i = 0; i < 8; i++)
#pragma unroll
                for (int j = 0; j < 8; j++)
                    acc[i][j] += ra[i] * rb[j];
        }
        __syncthreads();
    }

    // write back
#pragma unroll
    for (int i = 0; i < 8; i++) {
        int row = bm + ((i < 4) ? (tr + i) : (64 + tr + i - 4));
        float4 v0, v1;
        v0.x = acc[i][0]; v0.y = acc[i][1]; v0.z = acc[i][2]; v0.w = acc[i][3];
        v1.x = acc[i][4]; v1.y = acc[i][5]; v1.z = acc[i][6]; v1.w = acc[i][7];
        *(float4*)&C[(size_t)row * N + bn + tc]      = v0;
        *(float4*)&C[(size_t)row * N + bn + tc + 64] = v1;
    }
}

// ---------------------------------------------------------------------------
// RoPE (neox style), in-place on q (heads 0..31) and k (heads 32..39) of g_qkv
// ---------------------------------------------------------------------------
__global__ __launch_bounds__(256) void rope_kernel(const int* __restrict__ positions)
{
    const int idx = blockIdx.x * 256 + threadIdx.x;
    const int total = NTOK * 40 * 64;   // 40 roped heads (32 q + 8 k), 64 pairs
    if (idx >= total) return;

    const int d  = idx & 63;
    const int h  = (idx >> 6) % 40;
    const int t  = idx / (64 * 40);
    const int s  = t & (SS - 1);

    const float pos = (float)positions[s];
    // inv_freq = 10000^(-2d/128); compute in double for max fidelity to ref
    const float inv = (float)pow(10000.0, -(double)(2 * d) / 128.0);
    const float freq = pos * inv;
    float sn, cn;
    sincosf(freq, &sn, &cn);

    const int base = (h < H) ? (h * D) : (K_OFF + (h - H) * D);
    float* row = g_qkv + (size_t)t * QKV_COLS + base;
    const float x1 = row[d];
    const float x2 = row[d + 64];
    row[d]      = x1 * cn - x2 * sn;
    row[d + 64] = x2 * cn + x1 * sn;
}

// ---------------------------------------------------------------------------
// Flash attention (causal, GQA). One block per (q_tile of 64, head, batch).
// 256 threads. Online softmax. Writes g_attn[token, h*128+d].
// smem: Q/K/V tiles 64x128 (pad 132), P 64x68, m/l/corr.
// ---------------------------------------------------------------------------
#define QS_STRIDE 132
#define PS_STRIDE 68
#define FLASH_SMEM ((3*64*QS_STRIDE + 64*PS_STRIDE + 3*64) * sizeof(float))

__global__ __launch_bounds__(256) void flash_kernel()
{
    const int qt = blockIdx.x;   // 0..31
    const int h  = blockIdx.y;   // 0..31
    const int b  = blockIdx.z;   // 0..1
    const int kvh = h >> 2;      // GQA: 4 q heads per kv head

    extern __shared__ float sm[];
    float* Qs = sm;                       // 64 * 132
    float* Ks = Qs + 64 * QS_STRIDE;
    float* Vs = Ks + 64 * QS_STRIDE;
    float* Ps = Vs + 64 * QS_STRIDE;      // 64 * 68
    float* Ms = Ps + 64 * PS_STRIDE;
    float* Ls = Ms + 64;
    float* Cs = Ls + 64;

    const int tid = threadIdx.x;
    const int r0 = (tid >> 4) << 2;   // 4 rows owned
    const int j0 = (tid & 15) << 2;   // 4 score cols owned
    const int c0 = (tid & 15) << 3;   // 8 output cols owned

    // load Q tile (pre-scaled)
    for (int i = tid; i < 64 * 128; i += 256) {
        int rr = i >> 7, cc = i & 127;
        Qs[rr * QS_STRIDE + cc] =
            g_qkv[(size_t)(b * SS + qt * 64 + rr) * QKV_COLS + h * D + cc] * SCALE;
    }
    if (tid < 64) { Ms[tid] = -1e30f; Ls[tid] = 0.f; }

    float O[4][8];
#pragma unroll
    for (int i = 0; i < 4; i++)
#pragma unroll
        for (int c = 0; c < 8; c++) O[i][c] = 0.f;
    __syncthreads();

    for (int kt = 0; kt <= qt; kt++) {
        // load K,V tiles
        for (int i = tid; i < 64 * 128; i += 256) {
            int rr = i >> 7, cc = i & 127;
            size_t base = (size_t)(b * SS + kt * 64 + rr) * QKV_COLS + kvh * D + cc;
            Ks[rr * QS_STRIDE + cc] = g_qkv[base + K_OFF];
            Vs[rr * QS_STRIDE + cc] = g_qkv[base + V_OFF];
        }
        __syncthreads();

        // scores: 4x4 per thread
        float s[4][4];
#pragma unroll
        for (int i = 0; i < 4; i++)
#pragma unroll
            for (int j = 0; j < 4; j++) s[i][j] = 0.f;

#pragma unroll 4
        for (int k = 0; k < 128; k += 4) {
            float4 qa[4], kb[4];
#pragma unroll
            for (int i = 0; i < 4; i++) qa[i] = *(float4*)&Qs[(r0 + i) * QS_STRIDE + k];
#pragma unroll
            for (int j = 0; j < 4; j++) kb[j] = *(float4*)&Ks[(j0 + j) * QS_STRIDE + k];
#pragma unroll
            for (int i = 0; i < 4; i++)
#pragma unroll
                for (int j = 0; j < 4; j++)
                    s[i][j] += qa[i].x * kb[j].x + qa[i].y * kb[j].y
                             + qa[i].z * kb[j].z + qa[i].w * kb[j].w;
        }

        // causal mask + store to Ps
#pragma unroll
        for (int i = 0; i < 4; i++) {
            int qg = qt * 64 + r0 + i;
#pragma unroll
            for (int j = 0; j < 4; j++) {
                int kg = kt * 64 + j0 + j;
                Ps[(r0 + i) * PS_STRIDE + j0 + j] = (kg <= qg) ? s[i][j] : -1e30f;
            }
        }
        __syncthreads();

        // online softmax (one thread per row)
        if (tid < 64) {
            const int rr = tid;
            float m_old = Ms[rr];
            float m_new = m_old;
#pragma unroll 8
            for (int j = 0; j < 64; j++)
                m_new = fmaxf(m_new, Ps[rr * PS_STRIDE + j]);
            float corr = __expf(m_old - m_new);
            float lsum = 0.f;
#pragma unroll 8
            for (int j = 0; j < 64; j++) {
                float p = __expf(Ps[rr * PS_STRIDE + j] - m_new);
                Ps[rr * PS_STRIDE + j] = p;
                lsum += p;
            }
            Ls[rr] = Ls[rr] * corr + lsum;
            Ms[rr] = m_new;
            Cs[rr] = corr;
        }
        __syncthreads();

        // rescale O, accumulate P @ V
#pragma unroll
        for (int i = 0; i < 4; i++) {
            float corr = Cs[r0 + i];
#pragma unroll
            for (int c = 0; c < 8; c++) O[i][c] *= corr;
        }
        for (int j = 0; j < 64; j++) {
            float4 v0 = *(float4*)&Vs[j * QS_STRIDE + c0];
            float4 v1 = *(float4*)&Vs[j * QS_STRIDE + c0 + 4];
#pragma unroll
            for (int i = 0; i < 4; i++) {
                float p = Ps[(r0 + i) * PS_STRIDE + j];
                O[i][0] += p * v0.x; O[i][1] += p * v0.y;
                O[i][2] += p * v0.z; O[i][3] += p * v0.w;
                O[i][4] += p * v1.x; O[i][5] += p * v1.y;
                O[i][6] += p * v1.z; O[i][7] += p * v1.w;
            }
        }
        __syncthreads();
    }

    // normalize and write out
#pragma unroll
    for (int i = 0; i < 4; i++) {
        float inv = 1.f / Ls[r0 + i];
        int tok = b * SS + qt * 64 + r0 + i;
        float4 o0, o1;
        o0.x = O[i][0] * inv; o0.y = O[i][1] * inv;
        o0.z = O[i][2] * inv; o0.w = O[i][3] * inv;
        o1.x = O[i][4] * inv; o1.y = O[i][5] * inv;
        o1.z = O[i][6] * inv; o1.w = O[i][7] * inv;
        *(float4*)&g_attn[(size_t)tok * (H*D) + h * D + c0]     = o0;
        *(float4*)&g_attn[(size_t)tok * (H*D) + h * D + c0 + 4] = o1;
    }
}

// ---------------------------------------------------------------------------
// launch
// ---------------------------------------------------------------------------
extern "C" void kernel_launch(void* const* d_in, const int* in_sizes, int n_in,
                              void* d_out, int out_size)
{
    const int*   positions = (const int*)  d_in[0];
    const float* hidden    = (const float*)d_in[1];
    const float* w_qkv     = (const float*)d_in[2];
    const float* w_o       = (const float*)d_in[3];
    float*       out       = (float*)d_out;

    float* qkv_ptr  = nullptr;
    float* attn_ptr = nullptr;
    cudaGetSymbolAddress((void**)&qkv_ptr,  g_qkv);
    cudaGetSymbolAddress((void**)&attn_ptr, g_attn);

    // 1) QKV projection: [4096,4096] @ [4096,6144]
    {
        dim3 grid(QKV_COLS / 128, NTOK / 128);
        sgemm_kernel<<<grid, 256>>>(hidden, w_qkv, qkv_ptr, NTOK, QKV_COLS, HIDDEN);
    }

    // 2) RoPE in place on q,k
    {
        int total = NTOK * 40 * 64;
        rope_kernel<<<(total + 255) / 256, 256>>>(positions);
    }

    // 3) flash attention
    {
        cudaFuncSetAttribute(flash_kernel,
                             cudaFuncAttributeMaxDynamicSharedMemorySize,
                             (int)FLASH_SMEM);
        dim3 grid(SS / 64, H, BB);
        flash_kernel<<<grid, 256, FLASH_SMEM>>>();
    }

    // 4) output projection: [4096,4096] @ [4096,4096] -> d_out
    {
        dim3 grid(HIDDEN / 128, NTOK / 128);
        sgemm_kernel<<<grid, 256>>>(attn_ptr, w_o, out, NTOK, HIDDEN, H*D);
    }
}

// round 2
// speedup vs baseline: 1.6183x; 1.6183x over previous
#include <cuda_runtime.h>
#include <cuda_bf16.h>
#include <math.h>

// Problem constants
#define BB 2
#define SS 2048
#define NTOK (BB*SS)            // 4096
#define HIDDEN 4096
#define H 32
#define HK 8
#define D 128
#define QKV_COLS ((H + 2*HK) * D)   // 6144
#define K_OFF (H*D)                 // 4096
#define V_OFF (H*D + HK*D)          // 5120
#define SCALE 0.08838834764831845f  // 1/sqrt(128)

// Scratch (static device globals — no runtime allocation)
__device__ float g_qkv[(size_t)NTOK * QKV_COLS];   // ~100 MB
__device__ float g_attn[(size_t)NTOK * (H*D)];     // ~67 MB

__device__ __forceinline__ unsigned f2tf32(float x) {
    unsigned r;
    asm("cvt.rna.tf32.f32 %0, %1;" : "=r"(r) : "f"(x));
    return r;
}

// ---------------------------------------------------------------------------
// TF32 tensor-core GEMM: C[M,N] = A[M,K] @ B[K,N], row-major fp32 in/out.
// 128x128 block tile, BK=32, 256 threads (8 warps), warp tile 64x32,
// mma.sync.aligned.m16n8k8.row.col.f32.tf32.tf32.f32.
// Requires M,N % 128 == 0, K % 32 == 0.
// ---------------------------------------------------------------------------
#define AS_STRIDE 36
#define BS_STRIDE 136

__global__ __launch_bounds__(256) void tf32_gemm_kernel(
    const float* __restrict__ A, const float* __restrict__ B,
    float* __restrict__ C, int M, int N, int K)
{
    __shared__ float As[128][AS_STRIDE];   // [m][k], tf32-converted bits
    __shared__ float Bs[32][BS_STRIDE];    // [k][n], tf32-converted bits

    const int tid  = threadIdx.x;
    const int wid  = tid >> 5;
    const int lane = tid & 31;
    const int g    = lane >> 2;   // group id 0..7
    const int tg   = lane & 3;    // thread-in-group 0..3

    const int wm = (wid & 1) * 64;   // warp M offset in block tile
    const int wn = (wid >> 1) * 32;  // warp N offset in block tile

    const int bm = blockIdx.y * 128;
    const int bn = blockIdx.x * 128;

    // staging mapping
    const int arow = tid >> 3;       // 0..31 (4 passes)
    const int ac4  = tid & 7;        // float4 column in A tile (k/4)
    const int brow = tid >> 5;       // 0..7 (4 passes)
    const int bc4  = tid & 31;       // float4 column in B tile (n/4)

    float acc[4][4][4];
#pragma unroll
    for (int i = 0; i < 4; i++)
#pragma unroll
        for (int j = 0; j < 4; j++)
#pragma unroll
            for (int c = 0; c < 4; c++) acc[i][j][c] = 0.f;

    for (int k0 = 0; k0 < K; k0 += 32) {
        // stage A tile (convert to tf32 bits)
#pragma unroll
        for (int p = 0; p < 4; p++) {
            float4 v = *(const float4*)&A[(size_t)(bm + arow + 32*p) * K + k0 + ac4*4];
            v.x = __uint_as_float(f2tf32(v.x));
            v.y = __uint_as_float(f2tf32(v.y));
            v.z = __uint_as_float(f2tf32(v.z));
            v.w = __uint_as_float(f2tf32(v.w));
            *(float4*)&As[arow + 32*p][ac4*4] = v;
        }
        // stage B tile
#pragma unroll
        for (int p = 0; p < 4; p++) {
            float4 v = *(const float4*)&B[(size_t)(k0 + brow + 8*p) * N + bn + bc4*4];
            v.x = __uint_as_float(f2tf32(v.x));
            v.y = __uint_as_float(f2tf32(v.y));
            v.z = __uint_as_float(f2tf32(v.z));
            v.w = __uint_as_float(f2tf32(v.w));
            *(float4*)&Bs[brow + 8*p][bc4*4] = v;
        }
        __syncthreads();

#pragma unroll
        for (int ks = 0; ks < 4; ks++) {
            unsigned a[4][4], b[4][2];
#pragma unroll
            for (int i = 0; i < 4; i++) {
                const int r = wm + i*16 + g;
                a[i][0] = __float_as_uint(As[r    ][ks*8 + tg    ]);
                a[i][1] = __float_as_uint(As[r + 8][ks*8 + tg    ]);
                a[i][2] = __float_as_uint(As[r    ][ks*8 + tg + 4]);
                a[i][3] = __float_as_uint(As[r + 8][ks*8 + tg + 4]);
            }
#pragma unroll
            for (int j = 0; j < 4; j++) {
                const int c = wn + j*8 + g;
                b[j][0] = __float_as_uint(Bs[ks*8 + tg    ][c]);
                b[j][1] = __float_as_uint(Bs[ks*8 + tg + 4][c]);
            }
#pragma unroll
            for (int i = 0; i < 4; i++)
#pragma unroll
                for (int j = 0; j < 4; j++) {
                    asm volatile(
                        "mma.sync.aligned.m16n8k8.row.col.f32.tf32.tf32.f32 "
                        "{%0,%1,%2,%3}, {%4,%5,%6,%7}, {%8,%9}, {%0,%1,%2,%3};"
                        : "+f"(acc[i][j][0]), "+f"(acc[i][j][1]),
                          "+f"(acc[i][j][2]), "+f"(acc[i][j][3])
                        : "r"(a[i][0]), "r"(a[i][1]), "r"(a[i][2]), "r"(a[i][3]),
                          "r"(b[j][0]), "r"(b[j][1]));
                }
        }
        __syncthreads();
    }

    // epilogue
#pragma unroll
    for (int i = 0; i < 4; i++)
#pragma unroll
        for (int j = 0; j < 4; j++) {
            const int row = bm + wm + i*16 + g;
            const int col = bn + wn + j*8 + tg*2;
            float2 v0 = make_float2(acc[i][j][0], acc[i][j][1]);
            float2 v1 = make_float2(acc[i][j][2], acc[i][j][3]);
            *(float2*)&C[(size_t)row       * N + col] = v0;
            *(float2*)&C[(size_t)(row + 8) * N + col] = v1;
        }
}

// ---------------------------------------------------------------------------
// RoPE (neox style), in-place on q (heads 0..31) and k (heads 32..39) of g_qkv
// ---------------------------------------------------------------------------
__global__ __launch_bounds__(256) void rope_kernel(const int* __restrict__ positions)
{
    const int idx = blockIdx.x * 256 + threadIdx.x;
    const int total = NTOK * 40 * 64;   // 40 roped heads (32 q + 8 k), 64 pairs
    if (idx >= total) return;

    const int d  = idx & 63;
    const int h  = (idx >> 6) % 40;
    const int t  = idx / (64 * 40);
    const int s  = t & (SS - 1);

    const float pos = (float)positions[s];
    const float inv = (float)pow(10000.0, -(double)(2 * d) / 128.0);
    const float freq = pos * inv;
    float sn, cn;
    sincosf(freq, &sn, &cn);

    const int base = (h < H) ? (h * D) : (K_OFF + (h - H) * D);
    float* row = g_qkv + (size_t)t * QKV_COLS + base;
    const float x1 = row[d];
    const float x2 = row[d + 64];
    row[d]      = x1 * cn - x2 * sn;
    row[d + 64] = x2 * cn + x1 * sn;
}

// ---------------------------------------------------------------------------
// Flash attention (causal, GQA). One block per (q_tile of 64, head, batch).
// ---------------------------------------------------------------------------
#define QS_STRIDE 132
#define PS_STRIDE 68
#define FLASH_SMEM ((3*64*QS_STRIDE + 64*PS_STRIDE + 3*64) * sizeof(float))

__global__ __launch_bounds__(256) void flash_kernel()
{
    const int qt = blockIdx.x;   // 0..31
    const int h  = blockIdx.y;   // 0..31
    const int b  = blockIdx.z;   // 0..1
    const int kvh = h >> 2;      // GQA: 4 q heads per kv head

    extern __shared__ float sm[];
    float* Qs = sm;                       // 64 * 132
    float* Ks = Qs + 64 * QS_STRIDE;
    float* Vs = Ks + 64 * QS_STRIDE;
    float* Ps = Vs + 64 * QS_STRIDE;      // 64 * 68
    float* Ms = Ps + 64 * PS_STRIDE;
    float* Ls = Ms + 64;
    float* Cs = Ls + 64;

    const int tid = threadIdx.x;
    const int r0 = (tid >> 4) << 2;   // 4 rows owned
    const int j0 = (tid & 15) << 2;   // 4 score cols owned
    const int c0 = (tid & 15) << 3;   // 8 output cols owned

    for (int i = tid; i < 64 * 128; i += 256) {
        int rr = i >> 7, cc = i & 127;
        Qs[rr * QS_STRIDE + cc] =
            g_qkv[(size_t)(b * SS + qt * 64 + rr) * QKV_COLS + h * D + cc] * SCALE;
    }
    if (tid < 64) { Ms[tid] = -1e30f; Ls[tid] = 0.f; }

    float O[4][8];
#pragma unroll
    for (int i = 0; i < 4; i++)
#pragma unroll
        for (int c = 0; c < 8; c++) O[i][c] = 0.f;
    __syncthreads();

    for (int kt = 0; kt <= qt; kt++) {
        for (int i = tid; i < 64 * 128; i += 256) {
            int rr = i >> 7, cc = i & 127;
            size_t base = (size_t)(b * SS + kt * 64 + rr) * QKV_COLS + kvh * D + cc;
            Ks[rr * QS_STRIDE + cc] = g_qkv[base + K_OFF];
            Vs[rr * QS_STRIDE + cc] = g_qkv[base + V_OFF];
        }
        __syncthreads();

        float s[4][4];
#pragma unroll
        for (int i = 0; i < 4; i++)
#pragma unroll
            for (int j = 0; j < 4; j++) s[i][j] = 0.f;

#pragma unroll 4
        for (int k = 0; k < 128; k += 4) {
            float4 qa[4], kb[4];
#pragma unroll
            for (int i = 0; i < 4; i++) qa[i] = *(float4*)&Qs[(r0 + i) * QS_STRIDE + k];
#pragma unroll
            for (int j = 0; j < 4; j++) kb[j] = *(float4*)&Ks[(j0 + j) * QS_STRIDE + k];
#pragma unroll
            for (int i = 0; i < 4; i++)
#pragma unroll
                for (int j = 0; j < 4; j++)
                    s[i][j] += qa[i].x * kb[j].x + qa[i].y * kb[j].y
                             + qa[i].z * kb[j].z + qa[i].w * kb[j].w;
        }

#pragma unroll
        for (int i = 0; i < 4; i++) {
            int qg = qt * 64 + r0 + i;
#pragma unroll
            for (int j = 0; j < 4; j++) {
                int kg = kt * 64 + j0 + j;
                Ps[(r0 + i) * PS_STRIDE + j0 + j] = (kg <= qg) ? s[i][j] : -1e30f;
            }
        }
        __syncthreads();

        if (tid < 64) {
            const int rr = tid;
            float m_old = Ms[rr];
            float m_new = m_old;
#pragma unroll 8
            for (int j = 0; j < 64; j++)
                m_new = fmaxf(m_new, Ps[rr * PS_STRIDE + j]);
            float corr = __expf(m_old - m_new);
            float lsum = 0.f;
#pragma unroll 8
            for (int j = 0; j < 64; j++) {
                float p = __expf(Ps[rr * PS_STRIDE + j] - m_new);
                Ps[rr * PS_STRIDE + j] = p;
                lsum += p;
            }
            Ls[rr] = Ls[rr] * corr + lsum;
            Ms[rr] = m_new;
            Cs[rr] = corr;
        }
        __syncthreads();

#pragma unroll
        for (int i = 0; i < 4; i++) {
            float corr = Cs[r0 + i];
#pragma unroll
            for (int c = 0; c < 8; c++) O[i][c] *= corr;
        }
        for (int j = 0; j < 64; j++) {
            float4 v0 = *(float4*)&Vs[j * QS_STRIDE + c0];
            float4 v1 = *(float4*)&Vs[j * QS_STRIDE + c0 + 4];
#pragma unroll
            for (int i = 0; i < 4; i++) {
                float p = Ps[(r0 + i) * PS_STRIDE + j];
                O[i][0] += p * v0.x; O[i][1] += p * v0.y;
                O[i][2] += p * v0.z; O[i][3] += p * v0.w;
                O[i][4] += p * v1.x; O[i][5] += p * v1.y;
                O[i][6] += p * v1.z; O[i][7] += p * v1.w;
            }
        }
        __syncthreads();
    }

#pragma unroll
    for (int i = 0; i < 4; i++) {
        float inv = 1.f / Ls[r0 + i];
        int tok = b * SS + qt * 64 + r0 + i;
        float4 o0, o1;
        o0.x = O[i][0] * inv; o0.y = O[i][1] * inv;
        o0.z = O[i][2] * inv; o0.w = O[i][3] * inv;
        o1.x = O[i][4] * inv; o1.y = O[i][5] * inv;
        o1.z = O[i][6] * inv; o1.w = O[i][7] * inv;
        *(float4*)&g_attn[(size_t)tok * (H*D) + h * D + c0]     = o0;
        *(float4*)&g_attn[(size_t)tok * (H*D) + h * D + c0 + 4] = o1;
    }
}

// ---------------------------------------------------------------------------
// launch
// ---------------------------------------------------------------------------
extern "C" void kernel_launch(void* const* d_in, const int* in_sizes, int n_in,
                              void* d_out, int out_size)
{
    const int*   positions = (const int*)  d_in[0];
    const float* hidden    = (const float*)d_in[1];
    const float* w_qkv     = (const float*)d_in[2];
    const float* w_o       = (const float*)d_in[3];
    float*       out       = (float*)d_out;

    float* qkv_ptr  = nullptr;
    float* attn_ptr = nullptr;
    cudaGetSymbolAddress((void**)&qkv_ptr,  g_qkv);
    cudaGetSymbolAddress((void**)&attn_ptr, g_attn);

    // 1) QKV projection: [4096,4096] @ [4096,6144]
    {
        dim3 grid(QKV_COLS / 128, NTOK / 128);
        tf32_gemm_kernel<<<grid, 256>>>(hidden, w_qkv, qkv_ptr, NTOK, QKV_COLS, HIDDEN);
    }

    // 2) RoPE in place on q,k
    {
        int total = NTOK * 40 * 64;
        rope_kernel<<<(total + 255) / 256, 256>>>(positions);
    }

    // 3) flash attention
    {
        cudaFuncSetAttribute(flash_kernel,
                             cudaFuncAttributeMaxDynamicSharedMemorySize,
                             (int)FLASH_SMEM);
        dim3 grid(SS / 64, H, BB);
        flash_kernel<<<grid, 256, FLASH_SMEM>>>();
    }

    // 4) output projection: [4096,4096] @ [4096,4096] -> d_out
    {
        dim3 grid(HIDDEN / 128, NTOK / 128);
        tf32_gemm_kernel<<<grid, 256>>>(attn_ptr, w_o, out, NTOK, HIDDEN, H*D);
    }
}

// round 3
// speedup vs baseline: 2.5078x; 1.5497x over previous
#include <cuda_runtime.h>
#include <cuda_bf16.h>
#include <math.h>

// Problem constants
#define BB 2
#define SS 2048
#define NTOK (BB*SS)            // 4096
#define HIDDEN 4096
#define H 32
#define HK 8
#define D 128
#define QKV_COLS ((H + 2*HK) * D)   // 6144
#define K_OFF (H*D)                 // 4096
#define V_OFF (H*D + HK*D)          // 5120
#define SCALE 0.08838834764831845f  // 1/sqrt(128)

// Scratch (static device globals — no runtime allocation)
__device__ float g_qkv[(size_t)NTOK * QKV_COLS];   // ~100 MB
__device__ float g_attn[(size_t)NTOK * (H*D)];     // ~67 MB

__device__ __forceinline__ unsigned f2tf32(float x) {
    unsigned r;
    asm("cvt.rna.tf32.f32 %0, %1;" : "=r"(r) : "f"(x));
    return r;
}

// ---------------------------------------------------------------------------
// TF32 tensor-core GEMM (unchanged from R2): C = A @ B row-major fp32.
// ---------------------------------------------------------------------------
#define AS_STRIDE 36
#define BS_STRIDE 136

__global__ __launch_bounds__(256) void tf32_gemm_kernel(
    const float* __restrict__ A, const float* __restrict__ B,
    float* __restrict__ C, int M, int N, int K)
{
    __shared__ float As[128][AS_STRIDE];
    __shared__ float Bs[32][BS_STRIDE];

    const int tid  = threadIdx.x;
    const int wid  = tid >> 5;
    const int lane = tid & 31;
    const int g    = lane >> 2;
    const int tg   = lane & 3;

    const int wm = (wid & 1) * 64;
    const int wn = (wid >> 1) * 32;

    const int bm = blockIdx.y * 128;
    const int bn = blockIdx.x * 128;

    const int arow = tid >> 3;
    const int ac4  = tid & 7;
    const int brow = tid >> 5;
    const int bc4  = tid & 31;

    float acc[4][4][4];
#pragma unroll
    for (int i = 0; i < 4; i++)
#pragma unroll
        for (int j = 0; j < 4; j++)
#pragma unroll
            for (int c = 0; c < 4; c++) acc[i][j][c] = 0.f;

    for (int k0 = 0; k0 < K; k0 += 32) {
#pragma unroll
        for (int p = 0; p < 4; p++) {
            float4 v = *(const float4*)&A[(size_t)(bm + arow + 32*p) * K + k0 + ac4*4];
            v.x = __uint_as_float(f2tf32(v.x));
            v.y = __uint_as_float(f2tf32(v.y));
            v.z = __uint_as_float(f2tf32(v.z));
            v.w = __uint_as_float(f2tf32(v.w));
            *(float4*)&As[arow + 32*p][ac4*4] = v;
        }
#pragma unroll
        for (int p = 0; p < 4; p++) {
            float4 v = *(const float4*)&B[(size_t)(k0 + brow + 8*p) * N + bn + bc4*4];
            v.x = __uint_as_float(f2tf32(v.x));
            v.y = __uint_as_float(f2tf32(v.y));
            v.z = __uint_as_float(f2tf32(v.z));
            v.w = __uint_as_float(f2tf32(v.w));
            *(float4*)&Bs[brow + 8*p][bc4*4] = v;
        }
        __syncthreads();

#pragma unroll
        for (int ks = 0; ks < 4; ks++) {
            unsigned a[4][4], b[4][2];
#pragma unroll
            for (int i = 0; i < 4; i++) {
                const int r = wm + i*16 + g;
                a[i][0] = __float_as_uint(As[r    ][ks*8 + tg    ]);
                a[i][1] = __float_as_uint(As[r + 8][ks*8 + tg    ]);
                a[i][2] = __float_as_uint(As[r    ][ks*8 + tg + 4]);
                a[i][3] = __float_as_uint(As[r + 8][ks*8 + tg + 4]);
            }
#pragma unroll
            for (int j = 0; j < 4; j++) {
                const int c = wn + j*8 + g;
                b[j][0] = __float_as_uint(Bs[ks*8 + tg    ][c]);
                b[j][1] = __float_as_uint(Bs[ks*8 + tg + 4][c]);
            }
#pragma unroll
            for (int i = 0; i < 4; i++)
#pragma unroll
                for (int j = 0; j < 4; j++) {
                    asm volatile(
                        "mma.sync.aligned.m16n8k8.row.col.f32.tf32.tf32.f32 "
                        "{%0,%1,%2,%3}, {%4,%5,%6,%7}, {%8,%9}, {%0,%1,%2,%3};"
                        : "+f"(acc[i][j][0]), "+f"(acc[i][j][1]),
                          "+f"(acc[i][j][2]), "+f"(acc[i][j][3])
                        : "r"(a[i][0]), "r"(a[i][1]), "r"(a[i][2]), "r"(a[i][3]),
                          "r"(b[j][0]), "r"(b[j][1]));
                }
        }
        __syncthreads();
    }

#pragma unroll
    for (int i = 0; i < 4; i++)
#pragma unroll
        for (int j = 0; j < 4; j++) {
            const int row = bm + wm + i*16 + g;
            const int col = bn + wn + j*8 + tg*2;
            float2 v0 = make_float2(acc[i][j][0], acc[i][j][1]);
            float2 v1 = make_float2(acc[i][j][2], acc[i][j][3]);
            *(float2*)&C[(size_t)row       * N + col] = v0;
            *(float2*)&C[(size_t)(row + 8) * N + col] = v1;
        }
}

// ---------------------------------------------------------------------------
// RoPE (unchanged)
// ---------------------------------------------------------------------------
__global__ __launch_bounds__(256) void rope_kernel(const int* __restrict__ positions)
{
    const int idx = blockIdx.x * 256 + threadIdx.x;
    const int total = NTOK * 40 * 64;
    if (idx >= total) return;

    const int d  = idx & 63;
    const int h  = (idx >> 6) % 40;
    const int t  = idx / (64 * 40);
    const int s  = t & (SS - 1);

    const float pos = (float)positions[s];
    const float inv = (float)pow(10000.0, -(double)(2 * d) / 128.0);
    const float freq = pos * inv;
    float sn, cn;
    sincosf(freq, &sn, &cn);

    const int base = (h < H) ? (h * D) : (K_OFF + (h - H) * D);
    float* row = g_qkv + (size_t)t * QKV_COLS + base;
    const float x1 = row[d];
    const float x2 = row[d + 64];
    row[d]      = x1 * cn - x2 * sn;
    row[d + 64] = x2 * cn + x1 * sn;
}

// ---------------------------------------------------------------------------
// Tensor-core flash attention, bf16 2-term split (3-MMA) for both QK^T and PV.
// 128 threads (4 warps). Block tile: 64 queries x 64 keys. Warp: 16 q-rows.
// ---------------------------------------------------------------------------
#define QSTR 136   // bf16 stride for Q/K tiles (64 rows x 128 cols)
#define VSTR 72    // bf16 stride for transposed V (128 rows x 64 cols)
#define FLASH2_SMEM ((4*64*QSTR + 2*128*VSTR) * sizeof(__nv_bfloat16))

__device__ __forceinline__ void mma_bf16(float* c, unsigned a0, unsigned a1,
                                         unsigned a2, unsigned a3,
                                         unsigned b0, unsigned b1)
{
    asm volatile(
        "mma.sync.aligned.m16n8k16.row.col.f32.bf16.bf16.f32 "
        "{%0,%1,%2,%3}, {%4,%5,%6,%7}, {%8,%9}, {%0,%1,%2,%3};"
        : "+f"(c[0]), "+f"(c[1]), "+f"(c[2]), "+f"(c[3])
        : "r"(a0), "r"(a1), "r"(a2), "r"(a3), "r"(b0), "r"(b1));
}

__device__ __forceinline__ unsigned pack2bf(float x, float y) {
    __nv_bfloat162 t = __floats2bfloat162_rn(x, y);  // .x = x (low half)
    return *(unsigned*)&t;
}

// split v into hi(bf16) + lo(bf16 of residual); store pairs
__device__ __forceinline__ void split_store2(__nv_bfloat16* hi, __nv_bfloat16* lo,
                                             int off, float x, float y)
{
    __nv_bfloat16 hx = __float2bfloat16(x), hy = __float2bfloat16(y);
    float rx = x - __bfloat162float(hx);
    float ry = y - __bfloat162float(hy);
    *(__nv_bfloat162*)&hi[off] = __nv_bfloat162(hx, hy);
    *(__nv_bfloat162*)&lo[off] = __floats2bfloat162_rn(rx, ry);
}

__global__ __launch_bounds__(128) void flash_tc_kernel()
{
    const int qt = blockIdx.x;   // 0..31
    const int h  = blockIdx.y;   // 0..31
    const int b  = blockIdx.z;   // 0..1
    const int kvh = h >> 2;

    extern __shared__ __nv_bfloat16 sm2[];
    __nv_bfloat16* Qhi = sm2;
    __nv_bfloat16* Qlo = Qhi + 64*QSTR;
    __nv_bfloat16* Khi = Qlo + 64*QSTR;
    __nv_bfloat16* Klo = Khi + 64*QSTR;
    __nv_bfloat16* Vth = Klo + 64*QSTR;   // transposed V hi: [d][key]
    __nv_bfloat16* Vtl = Vth + 128*VSTR;  // transposed V lo

    const int tid  = threadIdx.x;
    const int warp = tid >> 5;
    const int lane = tid & 31;
    const int g    = lane >> 2;
    const int tg   = lane & 3;

    // ---- stage Q (scaled, split) ----
    for (int i = tid; i < 64*32; i += 128) {
        const int row = i >> 5;
        const int c4  = (i & 31) * 4;
        float4 v = *(const float4*)&g_qkv[(size_t)(b*SS + qt*64 + row)*QKV_COLS + h*D + c4];
        v.x *= SCALE; v.y *= SCALE; v.z *= SCALE; v.w *= SCALE;
        split_store2(Qhi, Qlo, row*QSTR + c4,     v.x, v.y);
        split_store2(Qhi, Qlo, row*QSTR + c4 + 2, v.z, v.w);
    }

    float m0 = -1e30f, m1 = -1e30f, l0 = 0.f, l1 = 0.f;
    float oAcc[16][4];
#pragma unroll
    for (int dt = 0; dt < 16; dt++)
#pragma unroll
        for (int c = 0; c < 4; c++) oAcc[dt][c] = 0.f;

    const int row0 = warp*16 + g;   // local q row (c0,c1); row1 = row0+8

    for (int kt = 0; kt <= qt; kt++) {
        // ---- stage K (split) ----
        for (int i = tid; i < 64*32; i += 128) {
            const int row = i >> 5;
            const int c4  = (i & 31) * 4;
            float4 v = *(const float4*)&g_qkv[(size_t)(b*SS + kt*64 + row)*QKV_COLS
                                              + K_OFF + kvh*D + c4];
            split_store2(Khi, Klo, row*QSTR + c4,     v.x, v.y);
            split_store2(Khi, Klo, row*QSTR + c4 + 2, v.z, v.w);
        }
        // ---- stage V transposed (split) ----
        for (int i = tid; i < 64*32; i += 128) {
            const int key = i >> 5;
            const int dg  = i & 31;
            const size_t base = (size_t)(b*SS + kt*64 + key)*QKV_COLS + V_OFF + kvh*D + dg;
#pragma unroll
            for (int j = 0; j < 4; j++) {
                float x = g_qkv[base + 32*j];
                __nv_bfloat16 hx = __float2bfloat16(x);
                Vth[(dg + 32*j)*VSTR + key] = hx;
                Vtl[(dg + 32*j)*VSTR + key] = __float2bfloat16(x - __bfloat162float(hx));
            }
        }
        __syncthreads();

        // ---- S = Q @ K^T  (3-MMA bf16 split) ----
        float sAcc[8][4];
#pragma unroll
        for (int nt = 0; nt < 8; nt++)
#pragma unroll
            for (int c = 0; c < 4; c++) sAcc[nt][c] = 0.f;

#pragma unroll
        for (int kc = 0; kc < 8; kc++) {
            const int ko = kc*16 + tg*2;
            unsigned ah0 = *(unsigned*)&Qhi[(row0    )*QSTR + ko];
            unsigned ah1 = *(unsigned*)&Qhi[(row0 + 8)*QSTR + ko];
            unsigned ah2 = *(unsigned*)&Qhi[(row0    )*QSTR + ko + 8];
            unsigned ah3 = *(unsigned*)&Qhi[(row0 + 8)*QSTR + ko + 8];
            unsigned al0 = *(unsigned*)&Qlo[(row0    )*QSTR + ko];
            unsigned al1 = *(unsigned*)&Qlo[(row0 + 8)*QSTR + ko];
            unsigned al2 = *(unsigned*)&Qlo[(row0    )*QSTR + ko + 8];
            unsigned al3 = *(unsigned*)&Qlo[(row0 + 8)*QSTR + ko + 8];
#pragma unroll
            for (int nt = 0; nt < 8; nt++) {
                const int krow = (nt*8 + g)*QSTR + ko;
                unsigned bh0 = *(unsigned*)&Khi[krow];
                unsigned bh1 = *(unsigned*)&Khi[krow + 8];
                unsigned bl0 = *(unsigned*)&Klo[krow];
                unsigned bl1 = *(unsigned*)&Klo[krow + 8];
                mma_bf16(sAcc[nt], ah0, ah1, ah2, ah3, bh0, bh1);
                mma_bf16(sAcc[nt], ah0, ah1, ah2, ah3, bl0, bl1);
                mma_bf16(sAcc[nt], al0, al1, al2, al3, bh0, bh1);
            }
        }

        // ---- causal mask on diagonal tile ----
        if (kt == qt) {
#pragma unroll
            for (int nt = 0; nt < 8; nt++) {
                const int col = nt*8 + tg*2;
                if (col     > row0    ) sAcc[nt][0] = -1e30f;
                if (col + 1 > row0    ) sAcc[nt][1] = -1e30f;
                if (col     > row0 + 8) sAcc[nt][2] = -1e30f;
                if (col + 1 > row0 + 8) sAcc[nt][3] = -1e30f;
            }
        }

        // ---- online softmax (registers + quad shfl) ----
        float mt0 = -1e30f, mt1 = -1e30f;
#pragma unroll
        for (int nt = 0; nt < 8; nt++) {
            mt0 = fmaxf(mt0, fmaxf(sAcc[nt][0], sAcc[nt][1]));
            mt1 = fmaxf(mt1, fmaxf(sAcc[nt][2], sAcc[nt][3]));
        }
        mt0 = fmaxf(mt0, __shfl_xor_sync(0xffffffffu, mt0, 1));
        mt0 = fmaxf(mt0, __shfl_xor_sync(0xffffffffu, mt0, 2));
        mt1 = fmaxf(mt1, __shfl_xor_sync(0xffffffffu, mt1, 1));
        mt1 = fmaxf(mt1, __shfl_xor_sync(0xffffffffu, mt1, 2));

        const float mn0 = fmaxf(m0, mt0);
        const float mn1 = fmaxf(m1, mt1);
        const float cr0 = __expf(m0 - mn0);
        const float cr1 = __expf(m1 - mn1);

        float sum0 = 0.f, sum1 = 0.f;
#pragma unroll
        for (int nt = 0; nt < 8; nt++) {
            sAcc[nt][0] = __expf(sAcc[nt][0] - mn0);
            sAcc[nt][1] = __expf(sAcc[nt][1] - mn0);
            sAcc[nt][2] = __expf(sAcc[nt][2] - mn1);
            sAcc[nt][3] = __expf(sAcc[nt][3] - mn1);
            sum0 += sAcc[nt][0] + sAcc[nt][1];
            sum1 += sAcc[nt][2] + sAcc[nt][3];
        }
        l0 = l0 * cr0 + sum0;
        l1 = l1 * cr1 + sum1;
        m0 = mn0; m1 = mn1;

#pragma unroll
        for (int dt = 0; dt < 16; dt++) {
            oAcc[dt][0] *= cr0; oAcc[dt][1] *= cr0;
            oAcc[dt][2] *= cr1; oAcc[dt][3] *= cr1;
        }

        // ---- O += P @ V  (3-MMA bf16 split; P packed from sAcc registers) ----
#pragma unroll
        for (int kc = 0; kc < 4; kc++) {
            // hi/lo split of P fragments
            float p00 = sAcc[2*kc][0],   p01 = sAcc[2*kc][1];
            float p02 = sAcc[2*kc][2],   p03 = sAcc[2*kc][3];
            float p10 = sAcc[2*kc+1][0], p11 = sAcc[2*kc+1][1];
            float p12 = sAcc[2*kc+1][2], p13 = sAcc[2*kc+1][3];

            __nv_bfloat16 h00=__float2bfloat16(p00), h01=__float2bfloat16(p01);
            __nv_bfloat16 h02=__float2bfloat16(p02), h03=__float2bfloat16(p03);
            __nv_bfloat16 h10=__float2bfloat16(p10), h11=__float2bfloat16(p11);
            __nv_bfloat16 h12=__float2bfloat16(p12), h13=__float2bfloat16(p13);

            __nv_bfloat162 t0(h00,h01), t1(h02,h03), t2(h10,h11), t3(h12,h13);
            unsigned ah0 = *(unsigned*)&t0;   // (row g,   k tg*2..+1)
            unsigned ah1 = *(unsigned*)&t1;   // (row g+8, k tg*2..+1)
            unsigned ah2 = *(unsigned*)&t2;   // (row g,   k tg*2+8..)
            unsigned ah3 = *(unsigned*)&t3;   // (row g+8, k tg*2+8..)

            unsigned al0 = pack2bf(p00 - __bfloat162float(h00), p01 - __bfloat162float(h01));
            unsigned al1 = pack2bf(p02 - __bfloat162float(h02), p03 - __bfloat162float(h03));
            unsigned al2 = pack2bf(p10 - __bfloat162float(h10), p11 - __bfloat162float(h11));
            unsigned al3 = pack2bf(p12 - __bfloat162float(h12), p13 - __bfloat162float(h13));

#pragma unroll
            for (int dt = 0; dt < 16; dt++) {
                const int vrow = (dt*8 + g)*VSTR + kc*16 + tg*2;
                unsigned bh0 = *(unsigned*)&Vth[vrow];
                unsigned bh1 = *(unsigned*)&Vth[vrow + 8];
                unsigned bl0 = *(unsigned*)&Vtl[vrow];
                unsigned bl1 = *(unsigned*)&Vtl[vrow + 8];
                mma_bf16(oAcc[dt], ah0, ah1, ah2, ah3, bh0, bh1);
                mma_bf16(oAcc[dt], ah0, ah1, ah2, ah3, bl0, bl1);
                mma_bf16(oAcc[dt], al0, al1, al2, al3, bh0, bh1);
            }
        }
        __syncthreads();
    }

    // ---- finalize: reduce l over quad, normalize, store ----
    l0 += __shfl_xor_sync(0xffffffffu, l0, 1);
    l0 += __shfl_xor_sync(0xffffffffu, l0, 2);
    l1 += __shfl_xor_sync(0xffffffffu, l1, 1);
    l1 += __shfl_xor_sync(0xffffffffu, l1, 2);
    const float inv0 = 1.f / l0;
    const float inv1 = 1.f / l1;

    const int tok0 = b*SS + qt*64 + row0;
#pragma unroll
    for (int dt = 0; dt < 16; dt++) {
        const int col = h*D + dt*8 + tg*2;
        float2 v0 = make_float2(oAcc[dt][0]*inv0, oAcc[dt][1]*inv0);
        float2 v1 = make_float2(oAcc[dt][2]*inv1, oAcc[dt][3]*inv1);
        *(float2*)&g_attn[(size_t)tok0       * (H*D) + col] = v0;
        *(float2*)&g_attn[(size_t)(tok0 + 8) * (H*D) + col] = v1;
    }
}

// ---------------------------------------------------------------------------
// launch
// ---------------------------------------------------------------------------
extern "C" void kernel_launch(void* const* d_in, const int* in_sizes, int n_in,
                              void* d_out, int out_size)
{
    const int*   positions = (const int*)  d_in[0];
    const float* hidden    = (const float*)d_in[1];
    const float* w_qkv     = (const float*)d_in[2];
    const float* w_o       = (const float*)d_in[3];
    float*       out       = (float*)d_out;

    float* qkv_ptr  = nullptr;
    float* attn_ptr = nullptr;
    cudaGetSymbolAddress((void**)&qkv_ptr,  g_qkv);
    cudaGetSymbolAddress((void**)&attn_ptr, g_attn);

    // 1) QKV projection
    {
        dim3 grid(QKV_COLS / 128, NTOK / 128);
        tf32_gemm_kernel<<<grid, 256>>>(hidden, w_qkv, qkv_ptr, NTOK, QKV_COLS, HIDDEN);
    }

    // 2) RoPE
    {
        int total = NTOK * 40 * 64;
        rope_kernel<<<(total + 255) / 256, 256>>>(positions);
    }

    // 3) tensor-core flash attention
    {
        cudaFuncSetAttribute(flash_tc_kernel,
                             cudaFuncAttributeMaxDynamicSharedMemorySize,
                             (int)FLASH2_SMEM);
        dim3 grid(SS / 64, H, BB);
        flash_tc_kernel<<<grid, 128, FLASH2_SMEM>>>();
    }

    // 4) output projection
    {
        dim3 grid(HIDDEN / 128, NTOK / 128);
        tf32_gemm_kernel<<<grid, 256>>>(attn_ptr, w_o, out, NTOK, HIDDEN, H*D);
    }
}

// round 4
// speedup vs baseline: 2.8041x; 1.1181x over previous
#include <cuda_runtime.h>
#include <cuda_bf16.h>
#include <math.h>

// Problem constants
#define BB 2
#define SS 2048
#define NTOK (BB*SS)            // 4096
#define HIDDEN 4096
#define H 32
#define HK 8
#define D 128
#define QKV_COLS ((H + 2*HK) * D)   // 6144
#define K_OFF (H*D)                 // 4096
#define V_OFF (H*D + HK*D)          // 5120
#define SCALE 0.08838834764831845f  // 1/sqrt(128)

// Scratch (static device globals — no runtime allocation)
__device__ float g_qkv[(size_t)NTOK * QKV_COLS];   // ~100 MB
__device__ float g_attn[(size_t)NTOK * (H*D)];     // ~67 MB
// pre-split bf16 operands for flash attention
__device__ __nv_bfloat16 g_qh[(size_t)BB*H*SS*D];   // [b,h,s,d]
__device__ __nv_bfloat16 g_ql[(size_t)BB*H*SS*D];
__device__ __nv_bfloat16 g_kh[(size_t)BB*HK*SS*D];  // [b,kvh,s,d]
__device__ __nv_bfloat16 g_kl[(size_t)BB*HK*SS*D];
__device__ __nv_bfloat16 g_vh[(size_t)BB*HK*D*SS];  // [b,kvh,d,s] (transposed)
__device__ __nv_bfloat16 g_vl[(size_t)BB*HK*D*SS];

__device__ __forceinline__ unsigned f2tf32(float x) {
    unsigned r;
    asm("cvt.rna.tf32.f32 %0, %1;" : "=r"(r) : "f"(x));
    return r;
}

// ---------------------------------------------------------------------------
// TF32 tensor-core GEMM (unchanged): C = A @ B row-major fp32.
// ---------------------------------------------------------------------------
#define AS_STRIDE 36
#define BS_STRIDE 136

__global__ __launch_bounds__(256) void tf32_gemm_kernel(
    const float* __restrict__ A, const float* __restrict__ B,
    float* __restrict__ C, int M, int N, int K)
{
    __shared__ float As[128][AS_STRIDE];
    __shared__ float Bs[32][BS_STRIDE];

    const int tid  = threadIdx.x;
    const int wid  = tid >> 5;
    const int lane = tid & 31;
    const int g    = lane >> 2;
    const int tg   = lane & 3;

    const int wm = (wid & 1) * 64;
    const int wn = (wid >> 1) * 32;

    const int bm = blockIdx.y * 128;
    const int bn = blockIdx.x * 128;

    const int arow = tid >> 3;
    const int ac4  = tid & 7;
    const int brow = tid >> 5;
    const int bc4  = tid & 31;

    float acc[4][4][4];
#pragma unroll
    for (int i = 0; i < 4; i++)
#pragma unroll
        for (int j = 0; j < 4; j++)
#pragma unroll
            for (int c = 0; c < 4; c++) acc[i][j][c] = 0.f;

    for (int k0 = 0; k0 < K; k0 += 32) {
#pragma unroll
        for (int p = 0; p < 4; p++) {
            float4 v = *(const float4*)&A[(size_t)(bm + arow + 32*p) * K + k0 + ac4*4];
            v.x = __uint_as_float(f2tf32(v.x));
            v.y = __uint_as_float(f2tf32(v.y));
            v.z = __uint_as_float(f2tf32(v.z));
            v.w = __uint_as_float(f2tf32(v.w));
            *(float4*)&As[arow + 32*p][ac4*4] = v;
        }
#pragma unroll
        for (int p = 0; p < 4; p++) {
            float4 v = *(const float4*)&B[(size_t)(k0 + brow + 8*p) * N + bn + bc4*4];
            v.x = __uint_as_float(f2tf32(v.x));
            v.y = __uint_as_float(f2tf32(v.y));
            v.z = __uint_as_float(f2tf32(v.z));
            v.w = __uint_as_float(f2tf32(v.w));
            *(float4*)&Bs[brow + 8*p][bc4*4] = v;
        }
        __syncthreads();

#pragma unroll
        for (int ks = 0; ks < 4; ks++) {
            unsigned a[4][4], b[4][2];
#pragma unroll
            for (int i = 0; i < 4; i++) {
                const int r = wm + i*16 + g;
                a[i][0] = __float_as_uint(As[r    ][ks*8 + tg    ]);
                a[i][1] = __float_as_uint(As[r + 8][ks*8 + tg    ]);
                a[i][2] = __float_as_uint(As[r    ][ks*8 + tg + 4]);
                a[i][3] = __float_as_uint(As[r + 8][ks*8 + tg + 4]);
            }
#pragma unroll
            for (int j = 0; j < 4; j++) {
                const int c = wn + j*8 + g;
                b[j][0] = __float_as_uint(Bs[ks*8 + tg    ][c]);
                b[j][1] = __float_as_uint(Bs[ks*8 + tg + 4][c]);
            }
#pragma unroll
            for (int i = 0; i < 4; i++)
#pragma unroll
                for (int j = 0; j < 4; j++) {
                    asm volatile(
                        "mma.sync.aligned.m16n8k8.row.col.f32.tf32.tf32.f32 "
                        "{%0,%1,%2,%3}, {%4,%5,%6,%7}, {%8,%9}, {%0,%1,%2,%3};"
                        : "+f"(acc[i][j][0]), "+f"(acc[i][j][1]),
                          "+f"(acc[i][j][2]), "+f"(acc[i][j][3])
                        : "r"(a[i][0]), "r"(a[i][1]), "r"(a[i][2]), "r"(a[i][3]),
                          "r"(b[j][0]), "r"(b[j][1]));
                }
        }
        __syncthreads();
    }

#pragma unroll
    for (int i = 0; i < 4; i++)
#pragma unroll
        for (int j = 0; j < 4; j++) {
            const int row = bm + wm + i*16 + g;
            const int col = bn + wn + j*8 + tg*2;
            float2 v0 = make_float2(acc[i][j][0], acc[i][j][1]);
            float2 v1 = make_float2(acc[i][j][2], acc[i][j][3]);
            *(float2*)&C[(size_t)row       * N + col] = v0;
            *(float2*)&C[(size_t)(row + 8) * N + col] = v1;
        }
}

// ---------------------------------------------------------------------------
// prep_qk: RoPE + (scale for q) + bf16 hi/lo split, q/k -> head-major arrays
// ---------------------------------------------------------------------------
__global__ __launch_bounds__(256) void prep_qk_kernel(const int* __restrict__ positions)
{
    const int idx = blockIdx.x * 256 + threadIdx.x;
    const int total = NTOK * 40 * 64;   // 40 roped heads (32 q + 8 k), 64 pairs
    if (idx >= total) return;

    const int d  = idx & 63;
    const int h  = (idx >> 6) % 40;
    const int t  = idx / (64 * 40);
    const int b  = t / SS;
    const int s  = t & (SS - 1);

    const float pos = (float)positions[s];
    const float inv = (float)pow(10000.0, -(double)(2 * d) / 128.0);
    const float freq = pos * inv;
    float sn, cn;
    sincosf(freq, &sn, &cn);

    float x1, x2;
    if (h < H) {
        const float* row = g_qkv + (size_t)t * QKV_COLS + h * D;
        x1 = row[d]; x2 = row[d + 64];
    } else {
        const float* row = g_qkv + (size_t)t * QKV_COLS + K_OFF + (h - H) * D;
        x1 = row[d]; x2 = row[d + 64];
    }
    float y1 = x1 * cn - x2 * sn;
    float y2 = x2 * cn + x1 * sn;

    if (h < H) {
        y1 *= SCALE; y2 *= SCALE;
        const size_t base = ((size_t)(b * H + h) * SS + s) * D;
        __nv_bfloat16 h1 = __float2bfloat16(y1), h2 = __float2bfloat16(y2);
        g_qh[base + d]      = h1;
        g_qh[base + d + 64] = h2;
        g_ql[base + d]      = __float2bfloat16(y1 - __bfloat162float(h1));
        g_ql[base + d + 64] = __float2bfloat16(y2 - __bfloat162float(h2));
    } else {
        const size_t base = ((size_t)(b * HK + (h - H)) * SS + s) * D;
        __nv_bfloat16 h1 = __float2bfloat16(y1), h2 = __float2bfloat16(y2);
        g_kh[base + d]      = h1;
        g_kh[base + d + 64] = h2;
        g_kl[base + d]      = __float2bfloat16(y1 - __bfloat162float(h1));
        g_kl[base + d + 64] = __float2bfloat16(y2 - __bfloat162float(h2));
    }
}

// ---------------------------------------------------------------------------
// prep_v: transpose V to [b,kvh,d,s] with bf16 hi/lo split (32x32 smem tiles)
// ---------------------------------------------------------------------------
__global__ void prep_v_kernel()
{
    __shared__ float tile[32][33];

    const int s0 = blockIdx.x * 32;
    const int d0 = blockIdx.y * 32;
    const int bk = blockIdx.z;           // b*HK + kvh
    const int b  = bk / HK;
    const int kvh = bk % HK;

    const int tx = threadIdx.x;          // 0..31
    const int ty = threadIdx.y;          // 0..7

#pragma unroll
    for (int j = 0; j < 4; j++) {
        const int s = s0 + ty + 8*j;
        tile[ty + 8*j][tx] =
            g_qkv[(size_t)(b*SS + s) * QKV_COLS + V_OFF + kvh*D + d0 + tx];
    }
    __syncthreads();

#pragma unroll
    for (int j = 0; j < 4; j++) {
        const int d = d0 + ty + 8*j;
        const float x = tile[tx][ty + 8*j];
        const size_t o = ((size_t)(b*HK + kvh) * D + d) * SS + s0 + tx;
        __nv_bfloat16 hx = __float2bfloat16(x);
        g_vh[o] = hx;
        g_vl[o] = __float2bfloat16(x - __bfloat162float(hx));
    }
}

// ---------------------------------------------------------------------------
// Tensor-core flash attention, bf16 2-term split; operands pre-split in gmem.
// 128 threads (4 warps). Block tile: 64 queries x 64 keys. Warp: 16 q-rows.
// ---------------------------------------------------------------------------
#define QSTR 136   // bf16 stride for Q/K tiles (64 rows x 128 cols)
#define VSTR 72    // bf16 stride for transposed V (128 rows x 64 cols)
#define FLASH2_SMEM ((4*64*QSTR + 2*128*VSTR) * sizeof(__nv_bfloat16))

__device__ __forceinline__ void mma_bf16(float* c, unsigned a0, unsigned a1,
                                         unsigned a2, unsigned a3,
                                         unsigned b0, unsigned b1)
{
    asm volatile(
        "mma.sync.aligned.m16n8k16.row.col.f32.bf16.bf16.f32 "
        "{%0,%1,%2,%3}, {%4,%5,%6,%7}, {%8,%9}, {%0,%1,%2,%3};"
        : "+f"(c[0]), "+f"(c[1]), "+f"(c[2]), "+f"(c[3])
        : "r"(a0), "r"(a1), "r"(a2), "r"(a3), "r"(b0), "r"(b1));
}

__device__ __forceinline__ unsigned pack2bf(float x, float y) {
    __nv_bfloat162 t = __floats2bfloat162_rn(x, y);
    return *(unsigned*)&t;
}

__global__ __launch_bounds__(128) void flash_tc_kernel()
{
    const int qt = blockIdx.x;   // 0..31
    const int h  = blockIdx.y;   // 0..31
    const int b  = blockIdx.z;   // 0..1
    const int kvh = h >> 2;

    extern __shared__ __nv_bfloat16 sm2[];
    __nv_bfloat16* Qhi = sm2;
    __nv_bfloat16* Qlo = Qhi + 64*QSTR;
    __nv_bfloat16* Khi = Qlo + 64*QSTR;
    __nv_bfloat16* Klo = Khi + 64*QSTR;
    __nv_bfloat16* Vth = Klo + 64*QSTR;   // transposed V hi: [d][key]
    __nv_bfloat16* Vtl = Vth + 128*VSTR;

    const int tid  = threadIdx.x;
    const int warp = tid >> 5;
    const int lane = tid & 31;
    const int g    = lane >> 2;
    const int tg   = lane & 3;

    // ---- stage Q (pure copy, 16B chunks): 64 rows x 16 uint4 per array ----
    {
        const __nv_bfloat16* srcs[2] = {
            g_qh + ((size_t)(b*H + h) * SS + qt*64) * D,
            g_ql + ((size_t)(b*H + h) * SS + qt*64) * D };
        __nv_bfloat16* dsts[2] = { Qhi, Qlo };
#pragma unroll
        for (int a = 0; a < 2; a++)
            for (int i = tid; i < 64*16; i += 128) {
                const int row = i >> 4, c8 = i & 15;
                *(uint4*)&dsts[a][row*QSTR + c8*8] =
                    *(const uint4*)&srcs[a][(size_t)row*D + c8*8];
            }
    }

    float m0 = -1e30f, m1 = -1e30f, l0 = 0.f, l1 = 0.f;
    float oAcc[16][4];
#pragma unroll
    for (int dt = 0; dt < 16; dt++)
#pragma unroll
        for (int c = 0; c < 4; c++) oAcc[dt][c] = 0.f;

    const int row0 = warp*16 + g;

    const __nv_bfloat16* kh_base = g_kh + (size_t)(b*HK + kvh) * SS * D;
    const __nv_bfloat16* kl_base = g_kl + (size_t)(b*HK + kvh) * SS * D;
    const __nv_bfloat16* vh_base = g_vh + (size_t)(b*HK + kvh) * D * SS;
    const __nv_bfloat16* vl_base = g_vl + (size_t)(b*HK + kvh) * D * SS;

    for (int kt = 0; kt <= qt; kt++) {
        // ---- stage K tiles (pure copy) ----
        for (int i = tid; i < 64*16; i += 128) {
            const int row = i >> 4, c8 = i & 15;
            const size_t src = (size_t)(kt*64 + row) * D + c8*8;
            *(uint4*)&Khi[row*QSTR + c8*8] = *(const uint4*)&kh_base[src];
            *(uint4*)&Klo[row*QSTR + c8*8] = *(const uint4*)&kl_base[src];
        }
        // ---- stage V tiles (pre-transposed; 128 rows x 8 uint4) ----
        for (int i = tid; i < 128*8; i += 128) {
            const int d = i >> 3, s8 = i & 7;
            const size_t src = (size_t)d * SS + kt*64 + s8*8;
            *(uint4*)&Vth[d*VSTR + s8*8] = *(const uint4*)&vh_base[src];
            *(uint4*)&Vtl[d*VSTR + s8*8] = *(const uint4*)&vl_base[src];
        }
        __syncthreads();

        // ---- S = Q @ K^T  (3-MMA bf16 split) ----
        float sAcc[8][4];
#pragma unroll
        for (int nt = 0; nt < 8; nt++)
#pragma unroll
            for (int c = 0; c < 4; c++) sAcc[nt][c] = 0.f;

#pragma unroll
        for (int kc = 0; kc < 8; kc++) {
            const int ko = kc*16 + tg*2;
            unsigned ah0 = *(unsigned*)&Qhi[(row0    )*QSTR + ko];
            unsigned ah1 = *(unsigned*)&Qhi[(row0 + 8)*QSTR + ko];
            unsigned ah2 = *(unsigned*)&Qhi[(row0    )*QSTR + ko + 8];
            unsigned ah3 = *(unsigned*)&Qhi[(row0 + 8)*QSTR + ko + 8];
            unsigned al0 = *(unsigned*)&Qlo[(row0    )*QSTR + ko];
            unsigned al1 = *(unsigned*)&Qlo[(row0 + 8)*QSTR + ko];
            unsigned al2 = *(unsigned*)&Qlo[(row0    )*QSTR + ko + 8];
            unsigned al3 = *(unsigned*)&Qlo[(row0 + 8)*QSTR + ko + 8];
#pragma unroll
            for (int nt = 0; nt < 8; nt++) {
                const int krow = (nt*8 + g)*QSTR + ko;
                unsigned bh0 = *(unsigned*)&Khi[krow];
                unsigned bh1 = *(unsigned*)&Khi[krow + 8];
                unsigned bl0 = *(unsigned*)&Klo[krow];
                unsigned bl1 = *(unsigned*)&Klo[krow + 8];
                mma_bf16(sAcc[nt], ah0, ah1, ah2, ah3, bh0, bh1);
                mma_bf16(sAcc[nt], ah0, ah1, ah2, ah3, bl0, bl1);
                mma_bf16(sAcc[nt], al0, al1, al2, al3, bh0, bh1);
            }
        }

        // ---- causal mask on diagonal tile ----
        if (kt == qt) {
#pragma unroll
            for (int nt = 0; nt < 8; nt++) {
                const int col = nt*8 + tg*2;
                if (col     > row0    ) sAcc[nt][0] = -1e30f;
                if (col + 1 > row0    ) sAcc[nt][1] = -1e30f;
                if (col     > row0 + 8) sAcc[nt][2] = -1e30f;
                if (col + 1 > row0 + 8) sAcc[nt][3] = -1e30f;
            }
        }

        // ---- online softmax (registers + quad shfl) ----
        float mt0 = -1e30f, mt1 = -1e30f;
#pragma unroll
        for (int nt = 0; nt < 8; nt++) {
            mt0 = fmaxf(mt0, fmaxf(sAcc[nt][0], sAcc[nt][1]));
            mt1 = fmaxf(mt1, fmaxf(sAcc[nt][2], sAcc[nt][3]));
        }
        mt0 = fmaxf(mt0, __shfl_xor_sync(0xffffffffu, mt0, 1));
        mt0 = fmaxf(mt0, __shfl_xor_sync(0xffffffffu, mt0, 2));
        mt1 = fmaxf(mt1, __shfl_xor_sync(0xffffffffu, mt1, 1));
        mt1 = fmaxf(mt1, __shfl_xor_sync(0xffffffffu, mt1, 2));

        const float mn0 = fmaxf(m0, mt0);
        const float mn1 = fmaxf(m1, mt1);
        const float cr0 = __expf(m0 - mn0);
        const float cr1 = __expf(m1 - mn1);

        float sum0 = 0.f, sum1 = 0.f;
#pragma unroll
        for (int nt = 0; nt < 8; nt++) {
            sAcc[nt][0] = __expf(sAcc[nt][0] - mn0);
            sAcc[nt][1] = __expf(sAcc[nt][1] - mn0);
            sAcc[nt][2] = __expf(sAcc[nt][2] - mn1);
            sAcc[nt][3] = __expf(sAcc[nt][3] - mn1);
            sum0 += sAcc[nt][0] + sAcc[nt][1];
            sum1 += sAcc[nt][2] + sAcc[nt][3];
        }
        l0 = l0 * cr0 + sum0;
        l1 = l1 * cr1 + sum1;
        m0 = mn0; m1 = mn1;

#pragma unroll
        for (int dt = 0; dt < 16; dt++) {
            oAcc[dt][0] *= cr0; oAcc[dt][1] *= cr0;
            oAcc[dt][2] *= cr1; oAcc[dt][3] *= cr1;
        }

        // ---- O += P @ V  (3-MMA bf16 split; P packed from registers) ----
#pragma unroll
        for (int kc = 0; kc < 4; kc++) {
            float p00 = sAcc[2*kc][0],   p01 = sAcc[2*kc][1];
            float p02 = sAcc[2*kc][2],   p03 = sAcc[2*kc][3];
            float p10 = sAcc[2*kc+1][0], p11 = sAcc[2*kc+1][1];
            float p12 = sAcc[2*kc+1][2], p13 = sAcc[2*kc+1][3];

            __nv_bfloat16 h00=__float2bfloat16(p00), h01=__float2bfloat16(p01);
            __nv_bfloat16 h02=__float2bfloat16(p02), h03=__float2bfloat16(p03);
            __nv_bfloat16 h10=__float2bfloat16(p10), h11=__float2bfloat16(p11);
            __nv_bfloat16 h12=__float2bfloat16(p12), h13=__float2bfloat16(p13);

            __nv_bfloat162 t0(h00,h01), t1(h02,h03), t2(h10,h11), t3(h12,h13);
            unsigned ah0 = *(unsigned*)&t0;
            unsigned ah1 = *(unsigned*)&t1;
            unsigned ah2 = *(unsigned*)&t2;
            unsigned ah3 = *(unsigned*)&t3;

            unsigned al0 = pack2bf(p00 - __bfloat162float(h00), p01 - __bfloat162float(h01));
            unsigned al1 = pack2bf(p02 - __bfloat162float(h02), p03 - __bfloat162float(h03));
            unsigned al2 = pack2bf(p10 - __bfloat162float(h10), p11 - __bfloat162float(h11));
            unsigned al3 = pack2bf(p12 - __bfloat162float(h12), p13 - __bfloat162float(h13));

#pragma unroll
            for (int dt = 0; dt < 16; dt++) {
                const int vrow = (dt*8 + g)*VSTR + kc*16 + tg*2;
                unsigned bh0 = *(unsigned*)&Vth[vrow];
                unsigned bh1 = *(unsigned*)&Vth[vrow + 8];
                unsigned bl0 = *(unsigned*)&Vtl[vrow];
                unsigned bl1 = *(unsigned*)&Vtl[vrow + 8];
                mma_bf16(oAcc[dt], ah0, ah1, ah2, ah3, bh0, bh1);
                mma_bf16(oAcc[dt], ah0, ah1, ah2, ah3, bl0, bl1);
                mma_bf16(oAcc[dt], al0, al1, al2, al3, bh0, bh1);
            }
        }
        __syncthreads();
    }

    // ---- finalize ----
    l0 += __shfl_xor_sync(0xffffffffu, l0, 1);
    l0 += __shfl_xor_sync(0xffffffffu, l0, 2);
    l1 += __shfl_xor_sync(0xffffffffu, l1, 1);
    l1 += __shfl_xor_sync(0xffffffffu, l1, 2);
    const float inv0 = 1.f / l0;
    const float inv1 = 1.f / l1;

    const int tok0 = b*SS + qt*64 + row0;
#pragma unroll
    for (int dt = 0; dt < 16; dt++) {
        const int col = h*D + dt*8 + tg*2;
        float2 v0 = make_float2(oAcc[dt][0]*inv0, oAcc[dt][1]*inv0);
        float2 v1 = make_float2(oAcc[dt][2]*inv1, oAcc[dt][3]*inv1);
        *(float2*)&g_attn[(size_t)tok0       * (H*D) + col] = v0;
        *(float2*)&g_attn[(size_t)(tok0 + 8) * (H*D) + col] = v1;
    }
}

// ---------------------------------------------------------------------------
// launch
// ---------------------------------------------------------------------------
extern "C" void kernel_launch(void* const* d_in, const int* in_sizes, int n_in,
                              void* d_out, int out_size)
{
    const int*   positions = (const int*)  d_in[0];
    const float* hidden    = (const float*)d_in[1];
    const float* w_qkv     = (const float*)d_in[2];
    const float* w_o       = (const float*)d_in[3];
    float*       out       = (float*)d_out;

    float* qkv_ptr  = nullptr;
    float* attn_ptr = nullptr;
    cudaGetSymbolAddress((void**)&qkv_ptr,  g_qkv);
    cudaGetSymbolAddress((void**)&attn_ptr, g_attn);

    // 1) QKV projection
    {
        dim3 grid(QKV_COLS / 128, NTOK / 128);
        tf32_gemm_kernel<<<grid, 256>>>(hidden, w_qkv, qkv_ptr, NTOK, QKV_COLS, HIDDEN);
    }

    // 2) prep: RoPE + scale + bf16 split (q,k) and transpose+split (v)
    {
        int total = NTOK * 40 * 64;
        prep_qk_kernel<<<(total + 255) / 256, 256>>>(positions);
        dim3 grid(SS/32, D/32, BB*HK);
        prep_v_kernel<<<grid, dim3(32, 8)>>>();
    }

    // 3) tensor-core flash attention
    {
        cudaFuncSetAttribute(flash_tc_kernel,
                             cudaFuncAttributeMaxDynamicSharedMemorySize,
                             (int)FLASH2_SMEM);
        dim3 grid(SS / 64, H, BB);
        flash_tc_kernel<<<grid, 128, FLASH2_SMEM>>>();
    }

    // 4) output projection
    {
        dim3 grid(HIDDEN / 128, NTOK / 128);
        tf32_gemm_kernel<<<grid, 256>>>(attn_ptr, w_o, out, NTOK, HIDDEN, H*D);
    }
}

// round 5
// speedup vs baseline: 3.5466x; 1.2648x over previous
#include <cuda_runtime.h>
#include <cuda_bf16.h>
#include <math.h>

// Problem constants
#define BB 2
#define SS 2048
#define NTOK (BB*SS)            // 4096
#define HIDDEN 4096
#define H 32
#define HK 8
#define D 128
#define QKV_COLS ((H + 2*HK) * D)   // 6144
#define K_OFF (H*D)                 // 4096
#define V_OFF (H*D + HK*D)          // 5120
#define SCALE 0.08838834764831845f  // 1/sqrt(128)

// Scratch (static device globals — no runtime allocation)
__device__ float g_qkv[(size_t)NTOK * QKV_COLS];   // ~100 MB
__device__ float g_attn[(size_t)NTOK * (H*D)];     // ~67 MB
// tf32-preconverted GEMM operands (reused across both GEMMs)
__device__ float g_tfA[(size_t)NTOK * HIDDEN];         // 67 MB
__device__ float g_tfB[(size_t)HIDDEN * QKV_COLS];     // 100 MB
// RoPE cos/sin table
__device__ float g_cosT[SS * 64];
__device__ float g_sinT[SS * 64];
// pre-split bf16 operands for flash attention
__device__ __nv_bfloat16 g_qh[(size_t)BB*H*SS*D];   // [b,h,s,d]
__device__ __nv_bfloat16 g_ql[(size_t)BB*H*SS*D];
__device__ __nv_bfloat16 g_kh[(size_t)BB*HK*SS*D];  // [b,kvh,s,d]
__device__ __nv_bfloat16 g_kl[(size_t)BB*HK*SS*D];
__device__ __nv_bfloat16 g_vh[(size_t)BB*HK*D*SS];  // [b,kvh,d,s] (transposed)
__device__ __nv_bfloat16 g_vl[(size_t)BB*HK*D*SS];

__device__ __forceinline__ unsigned f2tf32(float x) {
    unsigned r;
    asm("cvt.rna.tf32.f32 %0, %1;" : "=r"(r) : "f"(x));
    return r;
}

__device__ __forceinline__ unsigned smem_u32(const void* p) {
    return (unsigned)__cvta_generic_to_shared(p);
}
__device__ __forceinline__ void cp16(unsigned dst, const void* src) {
    asm volatile("cp.async.cg.shared.global [%0], [%1], 16;" :: "r"(dst), "l"(src));
}

// ---------------------------------------------------------------------------
// elementwise tf32 pre-conversion (round-to-nearest-even on mantissa)
// ---------------------------------------------------------------------------
__global__ __launch_bounds__(256) void tf32_convert_kernel(
    const float* __restrict__ in, float* __restrict__ out, int n4)
{
    const int i = blockIdx.x * 256 + threadIdx.x;
    if (i >= n4) return;
    float4 v = *(const float4*)&in[(size_t)i * 4];
    v.x = __uint_as_float(f2tf32(v.x));
    v.y = __uint_as_float(f2tf32(v.y));
    v.z = __uint_as_float(f2tf32(v.z));
    v.w = __uint_as_float(f2tf32(v.w));
    *(float4*)&out[(size_t)i * 4] = v;
}

// ---------------------------------------------------------------------------
// TF32 GEMM, cp.async double-buffered: C = A @ B, inputs pre-tf32-rounded.
// 128x128 block tile, BK=32, 256 threads (8 warps), warp tile 64x32.
// ---------------------------------------------------------------------------
#define GAS 36    // A smem stride (floats)
#define GBS 136   // B smem stride (floats)
#define GEMM_SMEM (2*(128*GAS + 32*GBS)*4)   // 71,680 B

__global__ __launch_bounds__(256) void tf32_gemm_db_kernel(
    const float* __restrict__ A, const float* __restrict__ B,
    float* __restrict__ C, int M, int N, int K)
{
    extern __shared__ float gsm[];
    float* As[2] = { gsm, gsm + 128*GAS + 32*GBS };
    float* Bs[2] = { gsm + 128*GAS, gsm + 2*128*GAS + 32*GBS };

    const int tid  = threadIdx.x;
    const int wid  = tid >> 5;
    const int lane = tid & 31;
    const int g    = lane >> 2;
    const int tg   = lane & 3;

    const int wm = (wid & 1) * 64;
    const int wn = (wid >> 1) * 32;

    const int bm = blockIdx.y * 128;
    const int bn = blockIdx.x * 128;

    // cp.async chunk mapping (4 chunks each for A and B per thread)
    // A: 1024 chunks: row = c>>3 (0..127), kc = c&7
    // B: 1024 chunks: row = c>>5 (0..31),  nc = c&31
    auto prefetch = [&](int k0, int buf) {
#pragma unroll
        for (int p = 0; p < 4; p++) {
            const int c = tid + 256*p;
            const int ar = c >> 3, akc = c & 7;
            cp16(smem_u32(&As[buf][ar*GAS + akc*4]),
                 &A[(size_t)(bm + ar) * K + k0 + akc*4]);
            const int br = c >> 5, bnc = c & 31;
            cp16(smem_u32(&Bs[buf][br*GBS + bnc*4]),
                 &B[(size_t)(k0 + br) * N + bn + bnc*4]);
        }
        asm volatile("cp.async.commit_group;");
    };

    float acc[4][4][4];
#pragma unroll
    for (int i = 0; i < 4; i++)
#pragma unroll
        for (int j = 0; j < 4; j++)
#pragma unroll
            for (int c = 0; c < 4; c++) acc[i][j][c] = 0.f;

    const int nIter = K / 32;
    prefetch(0, 0);

    for (int it = 0; it < nIter; it++) {
        const int buf = it & 1;
        asm volatile("cp.async.wait_group 0;");
        __syncthreads();

        if (it + 1 < nIter) prefetch((it + 1) * 32, buf ^ 1);

        const float* Ab = As[buf];
        const float* Bb = Bs[buf];
#pragma unroll
        for (int ks = 0; ks < 4; ks++) {
            unsigned a[4][4], b[4][2];
#pragma unroll
            for (int i = 0; i < 4; i++) {
                const int r = wm + i*16 + g;
                a[i][0] = __float_as_uint(Ab[(r    )*GAS + ks*8 + tg    ]);
                a[i][1] = __float_as_uint(Ab[(r + 8)*GAS + ks*8 + tg    ]);
                a[i][2] = __float_as_uint(Ab[(r    )*GAS + ks*8 + tg + 4]);
                a[i][3] = __float_as_uint(Ab[(r + 8)*GAS + ks*8 + tg + 4]);
            }
#pragma unroll
            for (int j = 0; j < 4; j++) {
                const int c = wn + j*8 + g;
                b[j][0] = __float_as_uint(Bb[(ks*8 + tg    )*GBS + c]);
                b[j][1] = __float_as_uint(Bb[(ks*8 + tg + 4)*GBS + c]);
            }
#pragma unroll
            for (int i = 0; i < 4; i++)
#pragma unroll
                for (int j = 0; j < 4; j++) {
                    asm volatile(
                        "mma.sync.aligned.m16n8k8.row.col.f32.tf32.tf32.f32 "
                        "{%0,%1,%2,%3}, {%4,%5,%6,%7}, {%8,%9}, {%0,%1,%2,%3};"
                        : "+f"(acc[i][j][0]), "+f"(acc[i][j][1]),
                          "+f"(acc[i][j][2]), "+f"(acc[i][j][3])
                        : "r"(a[i][0]), "r"(a[i][1]), "r"(a[i][2]), "r"(a[i][3]),
                          "r"(b[j][0]), "r"(b[j][1]));
                }
        }
        __syncthreads();   // all reads of buf done before it is refilled next+1
    }

#pragma unroll
    for (int i = 0; i < 4; i++)
#pragma unroll
        for (int j = 0; j < 4; j++) {
            const int row = bm + wm + i*16 + g;
            const int col = bn + wn + j*8 + tg*2;
            float2 v0 = make_float2(acc[i][j][0], acc[i][j][1]);
            float2 v1 = make_float2(acc[i][j][2], acc[i][j][3]);
            *(float2*)&C[(size_t)row       * N + col] = v0;
            *(float2*)&C[(size_t)(row + 8) * N + col] = v1;
        }
}

// ---------------------------------------------------------------------------
// RoPE table: cos/sin[s][d] computed once (double pow kept for exactness)
// ---------------------------------------------------------------------------
__global__ __launch_bounds__(256) void rope_table_kernel(const int* __restrict__ positions)
{
    const int idx = blockIdx.x * 256 + threadIdx.x;
    if (idx >= SS * 64) return;
    const int d = idx & 63;
    const int s = idx >> 6;
    const float pos = (float)positions[s];
    const float inv = (float)pow(10000.0, -(double)(2 * d) / 128.0);
    float sn, cn;
    sincosf(pos * inv, &sn, &cn);
    g_cosT[idx] = cn;
    g_sinT[idx] = sn;
}

// ---------------------------------------------------------------------------
// prep_qk: RoPE (table) + (scale for q) + bf16 hi/lo split -> head-major
// ---------------------------------------------------------------------------
__global__ __launch_bounds__(256) void prep_qk_kernel()
{
    const int idx = blockIdx.x * 256 + threadIdx.x;
    const int total = NTOK * 40 * 64;
    if (idx >= total) return;

    const int d  = idx & 63;
    const int h  = (idx >> 6) % 40;
    const int t  = idx / (64 * 40);
    const int b  = t / SS;
    const int s  = t & (SS - 1);

    const float cn = g_cosT[s * 64 + d];
    const float sn = g_sinT[s * 64 + d];

    float x1, x2;
    if (h < H) {
        const float* row = g_qkv + (size_t)t * QKV_COLS + h * D;
        x1 = row[d]; x2 = row[d + 64];
    } else {
        const float* row = g_qkv + (size_t)t * QKV_COLS + K_OFF + (h - H) * D;
        x1 = row[d]; x2 = row[d + 64];
    }
    float y1 = x1 * cn - x2 * sn;
    float y2 = x2 * cn + x1 * sn;

    if (h < H) {
        y1 *= SCALE; y2 *= SCALE;
        const size_t base = ((size_t)(b * H + h) * SS + s) * D;
        __nv_bfloat16 h1 = __float2bfloat16(y1), h2 = __float2bfloat16(y2);
        g_qh[base + d]      = h1;
        g_qh[base + d + 64] = h2;
        g_ql[base + d]      = __float2bfloat16(y1 - __bfloat162float(h1));
        g_ql[base + d + 64] = __float2bfloat16(y2 - __bfloat162float(h2));
    } else {
        const size_t base = ((size_t)(b * HK + (h - H)) * SS + s) * D;
        __nv_bfloat16 h1 = __float2bfloat16(y1), h2 = __float2bfloat16(y2);
        g_kh[base + d]      = h1;
        g_kh[base + d + 64] = h2;
        g_kl[base + d]      = __float2bfloat16(y1 - __bfloat162float(h1));
        g_kl[base + d + 64] = __float2bfloat16(y2 - __bfloat162float(h2));
    }
}

// ---------------------------------------------------------------------------
// prep_v: transpose V to [b,kvh,d,s] with bf16 hi/lo split (32x32 smem tiles)
// ---------------------------------------------------------------------------
__global__ void prep_v_kernel()
{
    __shared__ float tile[32][33];

    const int s0 = blockIdx.x * 32;
    const int d0 = blockIdx.y * 32;
    const int bk = blockIdx.z;
    const int b  = bk / HK;
    const int kvh = bk % HK;

    const int tx = threadIdx.x;
    const int ty = threadIdx.y;

#pragma unroll
    for (int j = 0; j < 4; j++) {
        const int s = s0 + ty + 8*j;
        tile[ty + 8*j][tx] =
            g_qkv[(size_t)(b*SS + s) * QKV_COLS + V_OFF + kvh*D + d0 + tx];
    }
    __syncthreads();

#pragma unroll
    for (int j = 0; j < 4; j++) {
        const int d = d0 + ty + 8*j;
        const float x = tile[tx][ty + 8*j];
        const size_t o = ((size_t)(b*HK + kvh) * D + d) * SS + s0 + tx;
        __nv_bfloat16 hx = __float2bfloat16(x);
        g_vh[o] = hx;
        g_vl[o] = __float2bfloat16(x - __bfloat162float(hx));
    }
}

// ---------------------------------------------------------------------------
// Tensor-core flash attention (unchanged from R4)
// ---------------------------------------------------------------------------
#define QSTR 136
#define VSTR 72
#define FLASH2_SMEM ((4*64*QSTR + 2*128*VSTR) * sizeof(__nv_bfloat16))

__device__ __forceinline__ void mma_bf16(float* c, unsigned a0, unsigned a1,
                                         unsigned a2, unsigned a3,
                                         unsigned b0, unsigned b1)
{
    asm volatile(
        "mma.sync.aligned.m16n8k16.row.col.f32.bf16.bf16.f32 "
        "{%0,%1,%2,%3}, {%4,%5,%6,%7}, {%8,%9}, {%0,%1,%2,%3};"
        : "+f"(c[0]), "+f"(c[1]), "+f"(c[2]), "+f"(c[3])
        : "r"(a0), "r"(a1), "r"(a2), "r"(a3), "r"(b0), "r"(b1));
}

__device__ __forceinline__ unsigned pack2bf(float x, float y) {
    __nv_bfloat162 t = __floats2bfloat162_rn(x, y);
    return *(unsigned*)&t;
}

__global__ __launch_bounds__(128) void flash_tc_kernel()
{
    const int qt = blockIdx.x;
    const int h  = blockIdx.y;
    const int b  = blockIdx.z;
    const int kvh = h >> 2;

    extern __shared__ __nv_bfloat16 sm2[];
    __nv_bfloat16* Qhi = sm2;
    __nv_bfloat16* Qlo = Qhi + 64*QSTR;
    __nv_bfloat16* Khi = Qlo + 64*QSTR;
    __nv_bfloat16* Klo = Khi + 64*QSTR;
    __nv_bfloat16* Vth = Klo + 64*QSTR;
    __nv_bfloat16* Vtl = Vth + 128*VSTR;

    const int tid  = threadIdx.x;
    const int warp = tid >> 5;
    const int lane = tid & 31;
    const int g    = lane >> 2;
    const int tg   = lane & 3;

    {
        const __nv_bfloat16* srcs[2] = {
            g_qh + ((size_t)(b*H + h) * SS + qt*64) * D,
            g_ql + ((size_t)(b*H + h) * SS + qt*64) * D };
        __nv_bfloat16* dsts[2] = { Qhi, Qlo };
#pragma unroll
        for (int a = 0; a < 2; a++)
            for (int i = tid; i < 64*16; i += 128) {
                const int row = i >> 4, c8 = i & 15;
                *(uint4*)&dsts[a][row*QSTR + c8*8] =
                    *(const uint4*)&srcs[a][(size_t)row*D + c8*8];
            }
    }

    float m0 = -1e30f, m1 = -1e30f, l0 = 0.f, l1 = 0.f;
    float oAcc[16][4];
#pragma unroll
    for (int dt = 0; dt < 16; dt++)
#pragma unroll
        for (int c = 0; c < 4; c++) oAcc[dt][c] = 0.f;

    const int row0 = warp*16 + g;

    const __nv_bfloat16* kh_base = g_kh + (size_t)(b*HK + kvh) * SS * D;
    const __nv_bfloat16* kl_base = g_kl + (size_t)(b*HK + kvh) * SS * D;
    const __nv_bfloat16* vh_base = g_vh + (size_t)(b*HK + kvh) * D * SS;
    const __nv_bfloat16* vl_base = g_vl + (size_t)(b*HK + kvh) * D * SS;

    for (int kt = 0; kt <= qt; kt++) {
        for (int i = tid; i < 64*16; i += 128) {
            const int row = i >> 4, c8 = i & 15;
            const size_t src = (size_t)(kt*64 + row) * D + c8*8;
            *(uint4*)&Khi[row*QSTR + c8*8] = *(const uint4*)&kh_base[src];
            *(uint4*)&Klo[row*QSTR + c8*8] = *(const uint4*)&kl_base[src];
        }
        for (int i = tid; i < 128*8; i += 128) {
            const int d = i >> 3, s8 = i & 7;
            const size_t src = (size_t)d * SS + kt*64 + s8*8;
            *(uint4*)&Vth[d*VSTR + s8*8] = *(const uint4*)&vh_base[src];
            *(uint4*)&Vtl[d*VSTR + s8*8] = *(const uint4*)&vl_base[src];
        }
        __syncthreads();

        float sAcc[8][4];
#pragma unroll
        for (int nt = 0; nt < 8; nt++)
#pragma unroll
            for (int c = 0; c < 4; c++) sAcc[nt][c] = 0.f;

#pragma unroll
        for (int kc = 0; kc < 8; kc++) {
            const int ko = kc*16 + tg*2;
            unsigned ah0 = *(unsigned*)&Qhi[(row0    )*QSTR + ko];
            unsigned ah1 = *(unsigned*)&Qhi[(row0 + 8)*QSTR + ko];
            unsigned ah2 = *(unsigned*)&Qhi[(row0    )*QSTR + ko + 8];
            unsigned ah3 = *(unsigned*)&Qhi[(row0 + 8)*QSTR + ko + 8];
            unsigned al0 = *(unsigned*)&Qlo[(row0    )*QSTR + ko];
            unsigned al1 = *(unsigned*)&Qlo[(row0 + 8)*QSTR + ko];
            unsigned al2 = *(unsigned*)&Qlo[(row0    )*QSTR + ko + 8];
            unsigned al3 = *(unsigned*)&Qlo[(row0 + 8)*QSTR + ko + 8];
#pragma unroll
            for (int nt = 0; nt < 8; nt++) {
                const int krow = (nt*8 + g)*QSTR + ko;
                unsigned bh0 = *(unsigned*)&Khi[krow];
                unsigned bh1 = *(unsigned*)&Khi[krow + 8];
                unsigned bl0 = *(unsigned*)&Klo[krow];
                unsigned bl1 = *(unsigned*)&Klo[krow + 8];
                mma_bf16(sAcc[nt], ah0, ah1, ah2, ah3, bh0, bh1);
                mma_bf16(sAcc[nt], ah0, ah1, ah2, ah3, bl0, bl1);
                mma_bf16(sAcc[nt], al0, al1, al2, al3, bh0, bh1);
            }
        }

        if (kt == qt) {
#pragma unroll
            for (int nt = 0; nt < 8; nt++) {
                const int col = nt*8 + tg*2;
                if (col     > row0    ) sAcc[nt][0] = -1e30f;
                if (col + 1 > row0    ) sAcc[nt][1] = -1e30f;
                if (col     > row0 + 8) sAcc[nt][2] = -1e30f;
                if (col + 1 > row0 + 8) sAcc[nt][3] = -1e30f;
            }
        }

        float mt0 = -1e30f, mt1 = -1e30f;
#pragma unroll
        for (int nt = 0; nt < 8; nt++) {
            mt0 = fmaxf(mt0, fmaxf(sAcc[nt][0], sAcc[nt][1]));
            mt1 = fmaxf(mt1, fmaxf(sAcc[nt][2], sAcc[nt][3]));
        }
        mt0 = fmaxf(mt0, __shfl_xor_sync(0xffffffffu, mt0, 1));
        mt0 = fmaxf(mt0, __shfl_xor_sync(0xffffffffu, mt0, 2));
        mt1 = fmaxf(mt1, __shfl_xor_sync(0xffffffffu, mt1, 1));
        mt1 = fmaxf(mt1, __shfl_xor_sync(0xffffffffu, mt1, 2));

        const float mn0 = fmaxf(m0, mt0);
        const float mn1 = fmaxf(m1, mt1);
        const float cr0 = __expf(m0 - mn0);
        const float cr1 = __expf(m1 - mn1);

        float sum0 = 0.f, sum1 = 0.f;
#pragma unroll
        for (int nt = 0; nt < 8; nt++) {
            sAcc[nt][0] = __expf(sAcc[nt][0] - mn0);
            sAcc[nt][1] = __expf(sAcc[nt][1] - mn0);
            sAcc[nt][2] = __expf(sAcc[nt][2] - mn1);
            sAcc[nt][3] = __expf(sAcc[nt][3] - mn1);
            sum0 += sAcc[nt][0] + sAcc[nt][1];
            sum1 += sAcc[nt][2] + sAcc[nt][3];
        }
        l0 = l0 * cr0 + sum0;
        l1 = l1 * cr1 + sum1;
        m0 = mn0; m1 = mn1;

#pragma unroll
        for (int dt = 0; dt < 16; dt++) {
            oAcc[dt][0] *= cr0; oAcc[dt][1] *= cr0;
            oAcc[dt][2] *= cr1; oAcc[dt][3] *= cr1;
        }

#pragma unroll
        for (int kc = 0; kc < 4; kc++) {
            float p00 = sAcc[2*kc][0],   p01 = sAcc[2*kc][1];
            float p02 = sAcc[2*kc][2],   p03 = sAcc[2*kc][3];
            float p10 = sAcc[2*kc+1][0], p11 = sAcc[2*kc+1][1];
            float p12 = sAcc[2*kc+1][2], p13 = sAcc[2*kc+1][3];

            __nv_bfloat16 h00=__float2bfloat16(p00), h01=__float2bfloat16(p01);
            __nv_bfloat16 h02=__float2bfloat16(p02), h03=__float2bfloat16(p03);
            __nv_bfloat16 h10=__float2bfloat16(p10), h11=__float2bfloat16(p11);
            __nv_bfloat16 h12=__float2bfloat16(p12), h13=__float2bfloat16(p13);

            __nv_bfloat162 t0(h00,h01), t1(h02,h03), t2(h10,h11), t3(h12,h13);
            unsigned ah0 = *(unsigned*)&t0;
            unsigned ah1 = *(unsigned*)&t1;
            unsigned ah2 = *(unsigned*)&t2;
            unsigned ah3 = *(unsigned*)&t3;

            unsigned al0 = pack2bf(p00 - __bfloat162float(h00), p01 - __bfloat162float(h01));
            unsigned al1 = pack2bf(p02 - __bfloat162float(h02), p03 - __bfloat162float(h03));
            unsigned al2 = pack2bf(p10 - __bfloat162float(h10), p11 - __bfloat162float(h11));
            unsigned al3 = pack2bf(p12 - __bfloat162float(h12), p13 - __bfloat162float(h13));

#pragma unroll
            for (int dt = 0; dt < 16; dt++) {
                const int vrow = (dt*8 + g)*VSTR + kc*16 + tg*2;
                unsigned bh0 = *(unsigned*)&Vth[vrow];
                unsigned bh1 = *(unsigned*)&Vth[vrow + 8];
                unsigned bl0 = *(unsigned*)&Vtl[vrow];
                unsigned bl1 = *(unsigned*)&Vtl[vrow + 8];
                mma_bf16(oAcc[dt], ah0, ah1, ah2, ah3, bh0, bh1);
                mma_bf16(oAcc[dt], ah0, ah1, ah2, ah3, bl0, bl1);
                mma_bf16(oAcc[dt], al0, al1, al2, al3, bh0, bh1);
            }
        }
        __syncthreads();
    }

    l0 += __shfl_xor_sync(0xffffffffu, l0, 1);
    l0 += __shfl_xor_sync(0xffffffffu, l0, 2);
    l1 += __shfl_xor_sync(0xffffffffu, l1, 1);
    l1 += __shfl_xor_sync(0xffffffffu, l1, 2);
    const float inv0 = 1.f / l0;
    const float inv1 = 1.f / l1;

    const int tok0 = b*SS + qt*64 + row0;
#pragma unroll
    for (int dt = 0; dt < 16; dt++) {
        const int col = h*D + dt*8 + tg*2;
        float2 v0 = make_float2(oAcc[dt][0]*inv0, oAcc[dt][1]*inv0);
        float2 v1 = make_float2(oAcc[dt][2]*inv1, oAcc[dt][3]*inv1);
        *(float2*)&g_attn[(size_t)tok0       * (H*D) + col] = v0;
        *(float2*)&g_attn[(size_t)(tok0 + 8) * (H*D) + col] = v1;
    }
}

// ---------------------------------------------------------------------------
// launch
// ---------------------------------------------------------------------------
extern "C" void kernel_launch(void* const* d_in, const int* in_sizes, int n_in,
                              void* d_out, int out_size)
{
    const int*   positions = (const int*)  d_in[0];
    const float* hidden    = (const float*)d_in[1];
    const float* w_qkv     = (const float*)d_in[2];
    const float* w_o       = (const float*)d_in[3];
    float*       out       = (float*)d_out;

    float* qkv_ptr  = nullptr;
    float* attn_ptr = nullptr;
    float* tfA_ptr  = nullptr;
    float* tfB_ptr  = nullptr;
    cudaGetSymbolAddress((void**)&qkv_ptr,  g_qkv);
    cudaGetSymbolAddress((void**)&attn_ptr, g_attn);
    cudaGetSymbolAddress((void**)&tfA_ptr,  g_tfA);
    cudaGetSymbolAddress((void**)&tfB_ptr,  g_tfB);

    cudaFuncSetAttribute(tf32_gemm_db_kernel,
                         cudaFuncAttributeMaxDynamicSharedMemorySize, GEMM_SMEM);
    cudaFuncSetAttribute(flash_tc_kernel,
                         cudaFuncAttributeMaxDynamicSharedMemorySize,
                         (int)FLASH2_SMEM);

    // 1) QKV projection (pre-convert operands, then cp.async GEMM)
    {
        int nA4 = NTOK * HIDDEN / 4;
        int nB4 = HIDDEN * QKV_COLS / 4;
        tf32_convert_kernel<<<(nA4 + 255)/256, 256>>>(hidden, tfA_ptr, nA4);
        tf32_convert_kernel<<<(nB4 + 255)/256, 256>>>(w_qkv,  tfB_ptr, nB4);
        dim3 grid(QKV_COLS / 128, NTOK / 128);
        tf32_gemm_db_kernel<<<grid, 256, GEMM_SMEM>>>(
            tfA_ptr, tfB_ptr, qkv_ptr, NTOK, QKV_COLS, HIDDEN);
    }

    // 2) prep: rope table, RoPE+scale+split (q,k), transpose+split (v)
    {
        rope_table_kernel<<<(SS*64 + 255)/256, 256>>>(positions);
        int total = NTOK * 40 * 64;
        prep_qk_kernel<<<(total + 255) / 256, 256>>>();
        dim3 grid(SS/32, D/32, BB*HK);
        prep_v_kernel<<<grid, dim3(32, 8)>>>();
    }

    // 3) tensor-core flash attention
    {
        dim3 grid(SS / 64, H, BB);
        flash_tc_kernel<<<grid, 128, FLASH2_SMEM>>>();
    }

    // 4) output projection
    {
        int nA4 = NTOK * (H*D) / 4;
        int nB4 = (H*D) * HIDDEN / 4;
        tf32_convert_kernel<<<(nA4 + 255)/256, 256>>>(attn_ptr, tfA_ptr, nA4);
        tf32_convert_kernel<<<(nB4 + 255)/256, 256>>>(w_o,      tfB_ptr, nB4);
        dim3 grid(HIDDEN / 128, NTOK / 128);
        tf32_gemm_db_kernel<<<grid, 256, GEMM_SMEM>>>(
            tfA_ptr, tfB_ptr, out, NTOK, HIDDEN, H*D);
    }
}

// round 6
// speedup vs baseline: 4.1536x; 1.1711x over previous
#include <cuda_runtime.h>
#include <cuda_bf16.h>
#include <math.h>

// Problem constants
#define BB 2
#define SS 2048
#define NTOK (BB*SS)            // 4096
#define HIDDEN 4096
#define H 32
#define HK 8
#define D 128
#define QKV_COLS ((H + 2*HK) * D)   // 6144
#define K_OFF (H*D)                 // 4096
#define V_OFF (H*D + HK*D)          // 5120
#define SCALE 0.08838834764831845f  // 1/sqrt(128)

// Scratch (static device globals — no runtime allocation)
__device__ float g_qkv[(size_t)NTOK * QKV_COLS];   // ~100 MB
__device__ float g_attn[(size_t)NTOK * (H*D)];     // ~67 MB
// RoPE cos/sin table
__device__ float g_cosT[SS * 64];
__device__ float g_sinT[SS * 64];
// pre-split bf16 operands for flash attention
__device__ __nv_bfloat16 g_qh[(size_t)BB*H*SS*D];   // [b,h,s,d]
__device__ __nv_bfloat16 g_ql[(size_t)BB*H*SS*D];
__device__ __nv_bfloat16 g_kh[(size_t)BB*HK*SS*D];  // [b,kvh,s,d]
__device__ __nv_bfloat16 g_kl[(size_t)BB*HK*SS*D];
__device__ __nv_bfloat16 g_vh[(size_t)BB*HK*D*SS];  // [b,kvh,d,s] (transposed)
__device__ __nv_bfloat16 g_vl[(size_t)BB*HK*D*SS];

__device__ __forceinline__ unsigned f2tf32(float x) {
    unsigned r;
    asm("cvt.rna.tf32.f32 %0, %1;" : "=r"(r) : "f"(x));
    return r;
}

// ---------------------------------------------------------------------------
// TF32 tensor-core GEMM (R2-proven): C = A @ B row-major fp32.
// 128x128 block tile, BK=32, 256 threads (8 warps), warp tile 64x32.
// ---------------------------------------------------------------------------
#define AS_STRIDE 36
#define BS_STRIDE 136

__global__ __launch_bounds__(256) void tf32_gemm_kernel(
    const float* __restrict__ A, const float* __restrict__ B,
    float* __restrict__ C, int M, int N, int K)
{
    __shared__ float As[128][AS_STRIDE];
    __shared__ float Bs[32][BS_STRIDE];

    const int tid  = threadIdx.x;
    const int wid  = tid >> 5;
    const int lane = tid & 31;
    const int g    = lane >> 2;
    const int tg   = lane & 3;

    const int wm = (wid & 1) * 64;
    const int wn = (wid >> 1) * 32;

    const int bm = blockIdx.y * 128;
    const int bn = blockIdx.x * 128;

    const int arow = tid >> 3;
    const int ac4  = tid & 7;
    const int brow = tid >> 5;
    const int bc4  = tid & 31;

    float acc[4][4][4];
#pragma unroll
    for (int i = 0; i < 4; i++)
#pragma unroll
        for (int j = 0; j < 4; j++)
#pragma unroll
            for (int c = 0; c < 4; c++) acc[i][j][c] = 0.f;

    for (int k0 = 0; k0 < K; k0 += 32) {
#pragma unroll
        for (int p = 0; p < 4; p++) {
            float4 v = *(const float4*)&A[(size_t)(bm + arow + 32*p) * K + k0 + ac4*4];
            v.x = __uint_as_float(f2tf32(v.x));
            v.y = __uint_as_float(f2tf32(v.y));
            v.z = __uint_as_float(f2tf32(v.z));
            v.w = __uint_as_float(f2tf32(v.w));
            *(float4*)&As[arow + 32*p][ac4*4] = v;
        }
#pragma unroll
        for (int p = 0; p < 4; p++) {
            float4 v = *(const float4*)&B[(size_t)(k0 + brow + 8*p) * N + bn + bc4*4];
            v.x = __uint_as_float(f2tf32(v.x));
            v.y = __uint_as_float(f2tf32(v.y));
            v.z = __uint_as_float(f2tf32(v.z));
            v.w = __uint_as_float(f2tf32(v.w));
            *(float4*)&Bs[brow + 8*p][bc4*4] = v;
        }
        __syncthreads();

#pragma unroll
        for (int ks = 0; ks < 4; ks++) {
            unsigned a[4][4], b[4][2];
#pragma unroll
            for (int i = 0; i < 4; i++) {
                const int r = wm + i*16 + g;
                a[i][0] = __float_as_uint(As[r    ][ks*8 + tg    ]);
                a[i][1] = __float_as_uint(As[r + 8][ks*8 + tg    ]);
                a[i][2] = __float_as_uint(As[r    ][ks*8 + tg + 4]);
                a[i][3] = __float_as_uint(As[r + 8][ks*8 + tg + 4]);
            }
#pragma unroll
            for (int j = 0; j < 4; j++) {
                const int c = wn + j*8 + g;
                b[j][0] = __float_as_uint(Bs[ks*8 + tg    ][c]);
                b[j][1] = __float_as_uint(Bs[ks*8 + tg + 4][c]);
            }
#pragma unroll
            for (int i = 0; i < 4; i++)
#pragma unroll
                for (int j = 0; j < 4; j++) {
                    asm volatile(
                        "mma.sync.aligned.m16n8k8.row.col.f32.tf32.tf32.f32 "
                        "{%0,%1,%2,%3}, {%4,%5,%6,%7}, {%8,%9}, {%0,%1,%2,%3};"
                        : "+f"(acc[i][j][0]), "+f"(acc[i][j][1]),
                          "+f"(acc[i][j][2]), "+f"(acc[i][j][3])
                        : "r"(a[i][0]), "r"(a[i][1]), "r"(a[i][2]), "r"(a[i][3]),
                          "r"(b[j][0]), "r"(b[j][1]));
                }
        }
        __syncthreads();
    }

#pragma unroll
    for (int i = 0; i < 4; i++)
#pragma unroll
        for (int j = 0; j < 4; j++) {
            const int row = bm + wm + i*16 + g;
            const int col = bn + wn + j*8 + tg*2;
            float2 v0 = make_float2(acc[i][j][0], acc[i][j][1]);
            float2 v1 = make_float2(acc[i][j][2], acc[i][j][3]);
            *(float2*)&C[(size_t)row       * N + col] = v0;
            *(float2*)&C[(size_t)(row + 8) * N + col] = v1;
        }
}

// ---------------------------------------------------------------------------
// RoPE table: cos/sin[s][d] computed once (double pow kept for exactness)
// ---------------------------------------------------------------------------
__global__ __launch_bounds__(256) void rope_table_kernel(const int* __restrict__ positions)
{
    const int idx = blockIdx.x * 256 + threadIdx.x;
    if (idx >= SS * 64) return;
    const int d = idx & 63;
    const int s = idx >> 6;
    const float pos = (float)positions[s];
    const float inv = (float)pow(10000.0, -(double)(2 * d) / 128.0);
    float sn, cn;
    sincosf(pos * inv, &sn, &cn);
    g_cosT[idx] = cn;
    g_sinT[idx] = sn;
}

// ---------------------------------------------------------------------------
// prep_qk: RoPE (table) + (scale for q) + bf16 hi/lo split -> head-major
// ---------------------------------------------------------------------------
__global__ __launch_bounds__(256) void prep_qk_kernel()
{
    const int idx = blockIdx.x * 256 + threadIdx.x;
    const int total = NTOK * 40 * 64;
    if (idx >= total) return;

    const int d  = idx & 63;
    const int h  = (idx >> 6) % 40;
    const int t  = idx / (64 * 40);
    const int b  = t / SS;
    const int s  = t & (SS - 1);

    const float cn = g_cosT[s * 64 + d];
    const float sn = g_sinT[s * 64 + d];

    float x1, x2;
    if (h < H) {
        const float* row = g_qkv + (size_t)t * QKV_COLS + h * D;
        x1 = row[d]; x2 = row[d + 64];
    } else {
        const float* row = g_qkv + (size_t)t * QKV_COLS + K_OFF + (h - H) * D;
        x1 = row[d]; x2 = row[d + 64];
    }
    float y1 = x1 * cn - x2 * sn;
    float y2 = x2 * cn + x1 * sn;

    if (h < H) {
        y1 *= SCALE; y2 *= SCALE;
        const size_t base = ((size_t)(b * H + h) * SS + s) * D;
        __nv_bfloat16 h1 = __float2bfloat16(y1), h2 = __float2bfloat16(y2);
        g_qh[base + d]      = h1;
        g_qh[base + d + 64] = h2;
        g_ql[base + d]      = __float2bfloat16(y1 - __bfloat162float(h1));
        g_ql[base + d + 64] = __float2bfloat16(y2 - __bfloat162float(h2));
    } else {
        const size_t base = ((size_t)(b * HK + (h - H)) * SS + s) * D;
        __nv_bfloat16 h1 = __float2bfloat16(y1), h2 = __float2bfloat16(y2);
        g_kh[base + d]      = h1;
        g_kh[base + d + 64] = h2;
        g_kl[base + d]      = __float2bfloat16(y1 - __bfloat162float(h1));
        g_kl[base + d + 64] = __float2bfloat16(y2 - __bfloat162float(h2));
    }
}

// ---------------------------------------------------------------------------
// prep_v: transpose V to [b,kvh,d,s] with bf16 hi/lo split (32x32 smem tiles)
// ---------------------------------------------------------------------------
__global__ void prep_v_kernel()
{
    __shared__ float tile[32][33];

    const int s0 = blockIdx.x * 32;
    const int d0 = blockIdx.y * 32;
    const int bk = blockIdx.z;
    const int b  = bk / HK;
    const int kvh = bk % HK;

    const int tx = threadIdx.x;
    const int ty = threadIdx.y;

#pragma unroll
    for (int j = 0; j < 4; j++) {
        const int s = s0 + ty + 8*j;
        tile[ty + 8*j][tx] =
            g_qkv[(size_t)(b*SS + s) * QKV_COLS + V_OFF + kvh*D + d0 + tx];
    }
    __syncthreads();

#pragma unroll
    for (int j = 0; j < 4; j++) {
        const int d = d0 + ty + 8*j;
        const float x = tile[tx][ty + 8*j];
        const size_t o = ((size_t)(b*HK + kvh) * D + d) * SS + s0 + tx;
        __nv_bfloat16 hx = __float2bfloat16(x);
        g_vh[o] = hx;
        g_vl[o] = __float2bfloat16(x - __bfloat162float(hx));
    }
}

// ---------------------------------------------------------------------------
// Tensor-core flash attention (R4-proven)
// ---------------------------------------------------------------------------
#define QSTR 136
#define VSTR 72
#define FLASH2_SMEM ((4*64*QSTR + 2*128*VSTR) * sizeof(__nv_bfloat16))

__device__ __forceinline__ void mma_bf16(float* c, unsigned a0, unsigned a1,
                                         unsigned a2, unsigned a3,
                                         unsigned b0, unsigned b1)
{
    asm volatile(
        "mma.sync.aligned.m16n8k16.row.col.f32.bf16.bf16.f32 "
        "{%0,%1,%2,%3}, {%4,%5,%6,%7}, {%8,%9}, {%0,%1,%2,%3};"
        : "+f"(c[0]), "+f"(c[1]), "+f"(c[2]), "+f"(c[3])
        : "r"(a0), "r"(a1), "r"(a2), "r"(a3), "r"(b0), "r"(b1));
}

__device__ __forceinline__ unsigned pack2bf(float x, float y) {
    __nv_bfloat162 t = __floats2bfloat162_rn(x, y);
    return *(unsigned*)&t;
}

__global__ __launch_bounds__(128) void flash_tc_kernel()
{
    const int qt = blockIdx.x;
    const int h  = blockIdx.y;
    const int b  = blockIdx.z;
    const int kvh = h >> 2;

    extern __shared__ __nv_bfloat16 sm2[];
    __nv_bfloat16* Qhi = sm2;
    __nv_bfloat16* Qlo = Qhi + 64*QSTR;
    __nv_bfloat16* Khi = Qlo + 64*QSTR;
    __nv_bfloat16* Klo = Khi + 64*QSTR;
    __nv_bfloat16* Vth = Klo + 64*QSTR;
    __nv_bfloat16* Vtl = Vth + 128*VSTR;

    const int tid  = threadIdx.x;
    const int warp = tid >> 5;
    const int lane = tid & 31;
    const int g    = lane >> 2;
    const int tg   = lane & 3;

    {
        const __nv_bfloat16* srcs[2] = {
            g_qh + ((size_t)(b*H + h) * SS + qt*64) * D,
            g_ql + ((size_t)(b*H + h) * SS + qt*64) * D };
        __nv_bfloat16* dsts[2] = { Qhi, Qlo };
#pragma unroll
        for (int a = 0; a < 2; a++)
            for (int i = tid; i < 64*16; i += 128) {
                const int row = i >> 4, c8 = i & 15;
                *(uint4*)&dsts[a][row*QSTR + c8*8] =
                    *(const uint4*)&srcs[a][(size_t)row*D + c8*8];
            }
    }

    float m0 = -1e30f, m1 = -1e30f, l0 = 0.f, l1 = 0.f;
    float oAcc[16][4];
#pragma unroll
    for (int dt = 0; dt < 16; dt++)
#pragma unroll
        for (int c = 0; c < 4; c++) oAcc[dt][c] = 0.f;

    const int row0 = warp*16 + g;

    const __nv_bfloat16* kh_base = g_kh + (size_t)(b*HK + kvh) * SS * D;
    const __nv_bfloat16* kl_base = g_kl + (size_t)(b*HK + kvh) * SS * D;
    const __nv_bfloat16* vh_base = g_vh + (size_t)(b*HK + kvh) * D * SS;
    const __nv_bfloat16* vl_base = g_vl + (size_t)(b*HK + kvh) * D * SS;

    for (int kt = 0; kt <= qt; kt++) {
        for (int i = tid; i < 64*16; i += 128) {
            const int row = i >> 4, c8 = i & 15;
            const size_t src = (size_t)(kt*64 + row) * D + c8*8;
            *(uint4*)&Khi[row*QSTR + c8*8] = *(const uint4*)&kh_base[src];
            *(uint4*)&Klo[row*QSTR + c8*8] = *(const uint4*)&kl_base[src];
        }
        for (int i = tid; i < 128*8; i += 128) {
            const int d = i >> 3, s8 = i & 7;
            const size_t src = (size_t)d * SS + kt*64 + s8*8;
            *(uint4*)&Vth[d*VSTR + s8*8] = *(const uint4*)&vh_base[src];
            *(uint4*)&Vtl[d*VSTR + s8*8] = *(const uint4*)&vl_base[src];
        }
        __syncthreads();

        float sAcc[8][4];
#pragma unroll
        for (int nt = 0; nt < 8; nt++)
#pragma unroll
            for (int c = 0; c < 4; c++) sAcc[nt][c] = 0.f;

#pragma unroll
        for (int kc = 0; kc < 8; kc++) {
            const int ko = kc*16 + tg*2;
            unsigned ah0 = *(unsigned*)&Qhi[(row0    )*QSTR + ko];
            unsigned ah1 = *(unsigned*)&Qhi[(row0 + 8)*QSTR + ko];
            unsigned ah2 = *(unsigned*)&Qhi[(row0    )*QSTR + ko + 8];
            unsigned ah3 = *(unsigned*)&Qhi[(row0 + 8)*QSTR + ko + 8];
            unsigned al0 = *(unsigned*)&Qlo[(row0    )*QSTR + ko];
            unsigned al1 = *(unsigned*)&Qlo[(row0 + 8)*QSTR + ko];
            unsigned al2 = *(unsigned*)&Qlo[(row0    )*QSTR + ko + 8];
            unsigned al3 = *(unsigned*)&Qlo[(row0 + 8)*QSTR + ko + 8];
#pragma unroll
            for (int nt = 0; nt < 8; nt++) {
                const int krow = (nt*8 + g)*QSTR + ko;
                unsigned bh0 = *(unsigned*)&Khi[krow];
                unsigned bh1 = *(unsigned*)&Khi[krow + 8];
                unsigned bl0 = *(unsigned*)&Klo[krow];
                unsigned bl1 = *(unsigned*)&Klo[krow + 8];
                mma_bf16(sAcc[nt], ah0, ah1, ah2, ah3, bh0, bh1);
                mma_bf16(sAcc[nt], ah0, ah1, ah2, ah3, bl0, bl1);
                mma_bf16(sAcc[nt], al0, al1, al2, al3, bh0, bh1);
            }
        }

        if (kt == qt) {
#pragma unroll
            for (int nt = 0; nt < 8; nt++) {
                const int col = nt*8 + tg*2;
                if (col     > row0    ) sAcc[nt][0] = -1e30f;
                if (col + 1 > row0    ) sAcc[nt][1] = -1e30f;
                if (col     > row0 + 8) sAcc[nt][2] = -1e30f;
                if (col + 1 > row0 + 8) sAcc[nt][3] = -1e30f;
            }
        }

        float mt0 = -1e30f, mt1 = -1e30f;
#pragma unroll
        for (int nt = 0; nt < 8; nt++) {
            mt0 = fmaxf(mt0, fmaxf(sAcc[nt][0], sAcc[nt][1]));
            mt1 = fmaxf(mt1, fmaxf(sAcc[nt][2], sAcc[nt][3]));
        }
        mt0 = fmaxf(mt0, __shfl_xor_sync(0xffffffffu, mt0, 1));
        mt0 = fmaxf(mt0, __shfl_xor_sync(0xffffffffu, mt0, 2));
        mt1 = fmaxf(mt1, __shfl_xor_sync(0xffffffffu, mt1, 1));
        mt1 = fmaxf(mt1, __shfl_xor_sync(0xffffffffu, mt1, 2));

        const float mn0 = fmaxf(m0, mt0);
        const float mn1 = fmaxf(m1, mt1);
        const float cr0 = __expf(m0 - mn0);
        const float cr1 = __expf(m1 - mn1);

        float sum0 = 0.f, sum1 = 0.f;
#pragma unroll
        for (int nt = 0; nt < 8; nt++) {
            sAcc[nt][0] = __expf(sAcc[nt][0] - mn0);
            sAcc[nt][1] = __expf(sAcc[nt][1] - mn0);
            sAcc[nt][2] = __expf(sAcc[nt][2] - mn1);
            sAcc[nt][3] = __expf(sAcc[nt][3] - mn1);
            sum0 += sAcc[nt][0] + sAcc[nt][1];
            sum1 += sAcc[nt][2] + sAcc[nt][3];
        }
        l0 = l0 * cr0 + sum0;
        l1 = l1 * cr1 + sum1;
        m0 = mn0; m1 = mn1;

#pragma unroll
        for (int dt = 0; dt < 16; dt++) {
            oAcc[dt][0] *= cr0; oAcc[dt][1] *= cr0;
            oAcc[dt][2] *= cr1; oAcc[dt][3] *= cr1;
        }

#pragma unroll
        for (int kc = 0; kc < 4; kc++) {
            float p00 = sAcc[2*kc][0],   p01 = sAcc[2*kc][1];
            float p02 = sAcc[2*kc][2],   p03 = sAcc[2*kc][3];
            float p10 = sAcc[2*kc+1][0], p11 = sAcc[2*kc+1][1];
            float p12 = sAcc[2*kc+1][2], p13 = sAcc[2*kc+1][3];

            __nv_bfloat16 h00=__float2bfloat16(p00), h01=__float2bfloat16(p01);
            __nv_bfloat16 h02=__float2bfloat16(p02), h03=__float2bfloat16(p03);
            __nv_bfloat16 h10=__float2bfloat16(p10), h11=__float2bfloat16(p11);
            __nv_bfloat16 h12=__float2bfloat16(p12), h13=__float2bfloat16(p13);

            __nv_bfloat162 t0(h00,h01), t1(h02,h03), t2(h10,h11), t3(h12,h13);
            unsigned ah0 = *(unsigned*)&t0;
            unsigned ah1 = *(unsigned*)&t1;
            unsigned ah2 = *(unsigned*)&t2;
            unsigned ah3 = *(unsigned*)&t3;

            unsigned al0 = pack2bf(p00 - __bfloat162float(h00), p01 - __bfloat162float(h01));
            unsigned al1 = pack2bf(p02 - __bfloat162float(h02), p03 - __bfloat162float(h03));
            unsigned al2 = pack2bf(p10 - __bfloat162float(h10), p11 - __bfloat162float(h11));
            unsigned al3 = pack2bf(p12 - __bfloat162float(h12), p13 - __bfloat162float(h13));

#pragma unroll
            for (int dt = 0; dt < 16; dt++) {
                const int vrow = (dt*8 + g)*VSTR + kc*16 + tg*2;
                unsigned bh0 = *(unsigned*)&Vth[vrow];
                unsigned bh1 = *(unsigned*)&Vth[vrow + 8];
                unsigned bl0 = *(unsigned*)&Vtl[vrow];
                unsigned bl1 = *(unsigned*)&Vtl[vrow + 8];
                mma_bf16(oAcc[dt], ah0, ah1, ah2, ah3, bh0, bh1);
                mma_bf16(oAcc[dt], ah0, ah1, ah2, ah3, bl0, bl1);
                mma_bf16(oAcc[dt], al0, al1, al2, al3, bh0, bh1);
            }
        }
        __syncthreads();
    }

    l0 += __shfl_xor_sync(0xffffffffu, l0, 1);
    l0 += __shfl_xor_sync(0xffffffffu, l0, 2);
    l1 += __shfl_xor_sync(0xffffffffu, l1, 1);
    l1 += __shfl_xor_sync(0xffffffffu, l1, 2);
    const float inv0 = 1.f / l0;
    const float inv1 = 1.f / l1;

    const int tok0 = b*SS + qt*64 + row0;
#pragma unroll
    for (int dt = 0; dt < 16; dt++) {
        const int col = h*D + dt*8 + tg*2;
        float2 v0 = make_float2(oAcc[dt][0]*inv0, oAcc[dt][1]*inv0);
        float2 v1 = make_float2(oAcc[dt][2]*inv1, oAcc[dt][3]*inv1);
        *(float2*)&g_attn[(size_t)tok0       * (H*D) + col] = v0;
        *(float2*)&g_attn[(size_t)(tok0 + 8) * (H*D) + col] = v1;
    }
}

// ---------------------------------------------------------------------------
// launch
// ---------------------------------------------------------------------------
extern "C" void kernel_launch(void* const* d_in, const int* in_sizes, int n_in,
                              void* d_out, int out_size)
{
    const int*   positions = (const int*)  d_in[0];
    const float* hidden    = (const float*)d_in[1];
    const float* w_qkv     = (const float*)d_in[2];
    const float* w_o       = (const float*)d_in[3];
    float*       out       = (float*)d_out;

    float* qkv_ptr  = nullptr;
    float* attn_ptr = nullptr;
    cudaGetSymbolAddress((void**)&qkv_ptr,  g_qkv);
    cudaGetSymbolAddress((void**)&attn_ptr, g_attn);

    cudaFuncSetAttribute(flash_tc_kernel,
                         cudaFuncAttributeMaxDynamicSharedMemorySize,
                         (int)FLASH2_SMEM);

    // 1) QKV projection
    {
        dim3 grid(QKV_COLS / 128, NTOK / 128);
        tf32_gemm_kernel<<<grid, 256>>>(hidden, w_qkv, qkv_ptr, NTOK, QKV_COLS, HIDDEN);
    }

    // 2) prep: rope table, RoPE+scale+split (q,k), transpose+split (v)
    {
        rope_table_kernel<<<(SS*64 + 255)/256, 256>>>(positions);
        int total = NTOK * 40 * 64;
        prep_qk_kernel<<<(total + 255) / 256, 256>>>();
        dim3 grid(SS/32, D/32, BB*HK);
        prep_v_kernel<<<grid, dim3(32, 8)>>>();
    }

    // 3) tensor-core flash attention
    {
        dim3 grid(SS / 64, H, BB);
        flash_tc_kernel<<<grid, 128, FLASH2_SMEM>>>();
    }

    // 4) output projection
    {
        dim3 grid(HIDDEN / 128, NTOK / 128);
        tf32_gemm_kernel<<<grid, 256>>>(attn_ptr, w_o, out, NTOK, HIDDEN, H*D);
    }
}